// round 1
// baseline (speedup 1.0000x reference)
#include <cuda_runtime.h>
#include <math.h>

// Problem constants
#define Bz   4
#define Nn   1024
#define Dd   1024
#define Hh   8
#define DKk  128
#define EPSf 1e-6f

// d_out layout: [out (B,N,D)] [attn_time (B,H,N,N)] [attn_feature (B,H,DK,DK)]
static const long long OUT_OFF = 0;
static const long long AT_OFF  = (long long)Bz * Nn * Dd;                 // 4194304
static const long long AF_OFF  = AT_OFF + (long long)Bz * Hh * Nn * Nn;  // 37748736

// Scratch (device globals; no dynamic allocation allowed)
#define PROJ_ELEMS ((long long)Bz * Hh * Nn * DKk)   // 4194304
__device__ float g_qt[PROJ_ELEMS];
__device__ float g_kt[PROJ_ELEMS];
__device__ float g_qf[PROJ_ELEMS];
__device__ float g_kf[PROJ_ELEMS];
__device__ float g_vv[PROJ_ELEMS];
__device__ float g_o1[PROJ_ELEMS];
__device__ float g_prefc[(long long)Bz * Nn * Dd];
__device__ float g_preln[(long long)Bz * Nn * Dd];

__device__ __forceinline__ long long zoff(int z, int div, long long shi, long long slo) {
    return (long long)(z / div) * shi + (long long)(z % div) * slo;
}

// ---------------------------------------------------------------------------
// Tiled SGEMM, C = alpha * A * B^T (+R), A:[M,K] rm, B:[Nc,K] rm
// 64x64 tile, BK=16, 256 threads, 4x4 per thread.
// ---------------------------------------------------------------------------
#define BM 64
#define BN 64
#define BK 16

__global__ void gemm_tn(const float* __restrict__ A, const float* __restrict__ Bm,
                        float* __restrict__ C, const float* __restrict__ R,
                        int M, int Nc, int K, int lda, int ldb, int ldc,
                        int adiv, long long ahi, long long alo,
                        int bdiv, long long bhi, long long blo,
                        int cdiv, long long chi, long long clo,
                        float alpha) {
    __shared__ float As[BK][BM];
    __shared__ float Bs[BK][BN];
    const int tid = threadIdx.x;
    const int tx = tid & 15, ty = tid >> 4;
    const int row0 = blockIdx.y * BM, col0 = blockIdx.x * BN;
    const int z = blockIdx.z;
    const float* Ab = A + zoff(z, adiv, ahi, alo);
    const float* Bb = Bm + zoff(z, bdiv, bhi, blo);
    float* Cb = C + zoff(z, cdiv, chi, clo);

    float acc[4][4] = {};
    for (int k0 = 0; k0 < K; k0 += BK) {
        #pragma unroll
        for (int e = tid; e < BM * BK; e += 256) {
            int i = e >> 4, k = e & 15;
            float v = 0.f;
            if (row0 + i < M) v = Ab[(long long)(row0 + i) * lda + k0 + k];
            As[k][i] = v;
        }
        #pragma unroll
        for (int e = tid; e < BN * BK; e += 256) {
            int j = e >> 4, k = e & 15;
            float v = 0.f;
            if (col0 + j < Nc) v = Bb[(long long)(col0 + j) * ldb + k0 + k];
            Bs[k][j] = v;
        }
        __syncthreads();
        #pragma unroll
        for (int k = 0; k < BK; k++) {
            float a[4], b[4];
            #pragma unroll
            for (int i = 0; i < 4; i++) a[i] = As[k][ty * 4 + i];
            #pragma unroll
            for (int j = 0; j < 4; j++) b[j] = Bs[k][tx * 4 + j];
            #pragma unroll
            for (int i = 0; i < 4; i++)
                #pragma unroll
                for (int j = 0; j < 4; j++)
                    acc[i][j] = fmaf(a[i], b[j], acc[i][j]);
        }
        __syncthreads();
    }
    #pragma unroll
    for (int i = 0; i < 4; i++) {
        int gi = row0 + ty * 4 + i;
        if (gi >= M) continue;
        #pragma unroll
        for (int j = 0; j < 4; j++) {
            int gj = col0 + tx * 4 + j;
            if (gj >= Nc) continue;
            float v = acc[i][j] * alpha;
            if (R) v += R[(long long)gi * ldc + gj];
            Cb[(long long)gi * ldc + gj] = v;
        }
    }
}

// C = alpha * A * B, A:[M,K] rm, B:[K,Nc] rm
__global__ void gemm_nn(const float* __restrict__ A, const float* __restrict__ Bm,
                        float* __restrict__ C,
                        int M, int Nc, int K, int lda, int ldb, int ldc,
                        int adiv, long long ahi, long long alo,
                        int bdiv, long long bhi, long long blo,
                        int cdiv, long long chi, long long clo,
                        float alpha) {
    __shared__ float As[BK][BM];
    __shared__ float Bs[BK][BN];
    const int tid = threadIdx.x;
    const int tx = tid & 15, ty = tid >> 4;
    const int row0 = blockIdx.y * BM, col0 = blockIdx.x * BN;
    const int z = blockIdx.z;
    const float* Ab = A + zoff(z, adiv, ahi, alo);
    const float* Bb = Bm + zoff(z, bdiv, bhi, blo);
    float* Cb = C + zoff(z, cdiv, chi, clo);

    float acc[4][4] = {};
    for (int k0 = 0; k0 < K; k0 += BK) {
        #pragma unroll
        for (int e = tid; e < BM * BK; e += 256) {
            int i = e >> 4, k = e & 15;
            float v = 0.f;
            if (row0 + i < M) v = Ab[(long long)(row0 + i) * lda + k0 + k];
            As[k][i] = v;
        }
        #pragma unroll
        for (int e = tid; e < BK * BN; e += 256) {
            int k = e >> 6, j = e & 63;
            float v = 0.f;
            if (col0 + j < Nc) v = Bb[(long long)(k0 + k) * ldb + col0 + j];
            Bs[k][j] = v;
        }
        __syncthreads();
        #pragma unroll
        for (int k = 0; k < BK; k++) {
            float a[4], b[4];
            #pragma unroll
            for (int i = 0; i < 4; i++) a[i] = As[k][ty * 4 + i];
            #pragma unroll
            for (int j = 0; j < 4; j++) b[j] = Bs[k][tx * 4 + j];
            #pragma unroll
            for (int i = 0; i < 4; i++)
                #pragma unroll
                for (int j = 0; j < 4; j++)
                    acc[i][j] = fmaf(a[i], b[j], acc[i][j]);
        }
        __syncthreads();
    }
    #pragma unroll
    for (int i = 0; i < 4; i++) {
        int gi = row0 + ty * 4 + i;
        if (gi >= M) continue;
        #pragma unroll
        for (int j = 0; j < 4; j++) {
            int gj = col0 + tx * 4 + j;
            if (gj >= Nc) continue;
            Cb[(long long)gi * ldc + gj] = acc[i][j] * alpha;
        }
    }
}

// ---------------------------------------------------------------------------
// attn_feature logits: S[z][d][e] = alpha * sum_n qf[z][n][d] * kf[z][n][e]
// One block per z = b*H+h, 256 threads, 8x8 per thread -> full 128x128 tile.
// ---------------------------------------------------------------------------
__global__ void attnfeat_kernel(const float* __restrict__ qf, const float* __restrict__ kf,
                                float* __restrict__ S, float alpha) {
    __shared__ float As[16][128];
    __shared__ float Bs[16][128];
    const int z = blockIdx.x;
    const int tid = threadIdx.x;
    const int tx = tid & 15, ty = tid >> 4;
    const float* A = qf + (long long)z * Nn * DKk;
    const float* Bp = kf + (long long)z * Nn * DKk;
    float* Sb = S + (long long)z * DKk * DKk;

    float acc[8][8] = {};
    for (int n0 = 0; n0 < Nn; n0 += 16) {
        #pragma unroll
        for (int e = tid; e < 16 * 128; e += 256) {
            int k = e >> 7, d = e & 127;
            As[k][d] = A[(long long)(n0 + k) * DKk + d];
            Bs[k][d] = Bp[(long long)(n0 + k) * DKk + d];
        }
        __syncthreads();
        #pragma unroll
        for (int k = 0; k < 16; k++) {
            float a[8], b[8];
            #pragma unroll
            for (int i = 0; i < 8; i++) { a[i] = As[k][ty * 8 + i]; b[i] = Bs[k][tx * 8 + i]; }
            #pragma unroll
            for (int i = 0; i < 8; i++)
                #pragma unroll
                for (int j = 0; j < 8; j++)
                    acc[i][j] = fmaf(a[i], b[j], acc[i][j]);
        }
        __syncthreads();
    }
    #pragma unroll
    for (int i = 0; i < 8; i++)
        #pragma unroll
        for (int j = 0; j < 8; j++)
            Sb[(long long)(ty * 8 + i) * DKk + tx * 8 + j] = acc[i][j] * alpha;
}

// ---------------------------------------------------------------------------
// Reductions
// ---------------------------------------------------------------------------
__device__ __forceinline__ float block_reduce(float v, bool is_max) {
    __shared__ float sh[32];
    int lane = threadIdx.x & 31, w = threadIdx.x >> 5;
    #pragma unroll
    for (int o = 16; o > 0; o >>= 1) {
        float o2 = __shfl_xor_sync(0xffffffff, v, o);
        v = is_max ? fmaxf(v, o2) : v + o2;
    }
    if (lane == 0) sh[w] = v;
    __syncthreads();
    int nw = (blockDim.x + 31) >> 5;
    v = (lane < nw) ? sh[lane] : (is_max ? -3.4e38f : 0.f);
    if (w == 0) {
        #pragma unroll
        for (int o = 16; o > 0; o >>= 1) {
            float o2 = __shfl_xor_sync(0xffffffff, v, o);
            v = is_max ? fmaxf(v, o2) : v + o2;
        }
        if (lane == 0) sh[0] = v;
    }
    __syncthreads();
    v = sh[0];
    __syncthreads();
    return v;
}

// masked softmax over rows of attn_time (in-place). Row = (b,h,n), 1024 elems, 256 thr.
__global__ void softmax_time_kernel(float* __restrict__ attn, const int* __restrict__ mask) {
    const int r = blockIdx.x;            // b*H*N + h*N + n
    const int b = r / (Hh * Nn);
    const int n = r % Nn;
    float* row = attn + (long long)r * Nn;
    const int* mrow = mask + ((long long)b * Nn + n) * Nn;
    const int t = threadIdx.x;

    float x[4];
    float mx = -3.4e38f;
    #pragma unroll
    for (int i = 0; i < 4; i++) {
        int j = t + i * 256;
        float v = row[j];
        if (mrow[j] == 0) v = -1e9f;
        x[i] = v;
        mx = fmaxf(mx, v);
    }
    mx = block_reduce(mx, true);
    float s = 0.f;
    #pragma unroll
    for (int i = 0; i < 4; i++) { x[i] = __expf(x[i] - mx); s += x[i]; }
    s = block_reduce(s, false);
    float inv = 1.f / s;
    #pragma unroll
    for (int i = 0; i < 4; i++) row[t + i * 256] = x[i] * inv;
}

// softmax over last axis of attn_feature (in-place). Row = 128 elems, 128 thr.
__global__ void softmax_feat_kernel(float* __restrict__ S) {
    float* row = S + (long long)blockIdx.x * DKk;
    float v = row[threadIdx.x];
    float mx = block_reduce(v, true);
    float e = __expf(v - mx);
    float s = block_reduce(e, false);
    row[threadIdx.x] = e / s;
}

// LayerNorm over last dim (1024). 256 thr/row.
__global__ void layernorm_kernel(const float* __restrict__ X, float* __restrict__ O,
                                 const float* __restrict__ gamma, const float* __restrict__ beta) {
    const int r = blockIdx.x;
    const float* row = X + (long long)r * Dd;
    float* orow = O + (long long)r * Dd;
    const int t = threadIdx.x;
    float x[4];
    float s = 0.f, s2 = 0.f;
    #pragma unroll
    for (int i = 0; i < 4; i++) {
        x[i] = row[t + i * 256];
        s += x[i];
        s2 += x[i] * x[i];
    }
    s = block_reduce(s, false);
    s2 = block_reduce(s2, false);
    float mean = s * (1.f / Dd);
    float var = s2 * (1.f / Dd) - mean * mean;
    float inv = rsqrtf(var + EPSf);
    #pragma unroll
    for (int i = 0; i < 4; i++) {
        int j = t + i * 256;
        orow[j] = (x[i] - mean) * inv * gamma[j] + beta[j];
    }
}

// ---------------------------------------------------------------------------
extern "C" void kernel_launch(void* const* d_in, const int* in_sizes, int n_in,
                              void* d_out, int out_size) {
    const float* q_time    = (const float*)d_in[0];
    const float* k_time    = (const float*)d_in[1];
    const float* q_feature = (const float*)d_in[2];
    const float* k_feature = (const float*)d_in[3];
    const float* v         = (const float*)d_in[4];
    const int*   attn_mask = (const int*)  d_in[5];
    const float* w_qs_time = (const float*)d_in[6];
    const float* w_ks_time = (const float*)d_in[7];
    const float* w_qs_feat = (const float*)d_in[8];
    const float* w_ks_feat = (const float*)d_in[9];
    const float* w_vs      = (const float*)d_in[10];
    const float* w_fc      = (const float*)d_in[11];
    const float* ln_gamma  = (const float*)d_in[12];
    const float* ln_beta   = (const float*)d_in[13];
    float* out = (float*)d_out;

    float *qt, *kt, *qf, *kf, *vv, *o1, *prefc, *preln;
    cudaGetSymbolAddress((void**)&qt,    g_qt);
    cudaGetSymbolAddress((void**)&kt,    g_kt);
    cudaGetSymbolAddress((void**)&qf,    g_qf);
    cudaGetSymbolAddress((void**)&kf,    g_kf);
    cudaGetSymbolAddress((void**)&vv,    g_vv);
    cudaGetSymbolAddress((void**)&o1,    g_o1);
    cudaGetSymbolAddress((void**)&prefc, g_prefc);
    cudaGetSymbolAddress((void**)&preln, g_preln);

    const float inv_temp = 1.0f / sqrtf((float)DKk);
    const int Z = Bz * Hh;  // 32

    // 1) Projections: [B,H,N,128] = X[B,N,D] @ W[h-block]^T, batched over (b,h)
    {
        dim3 grid(DKk / BN, Nn / BM, Z), blk(256);
        // A off: (z/H)*N*D ; B off: (z%H)*128*D ; C off: z*N*128
        gemm_tn<<<grid, blk>>>(q_time, w_qs_time, qt, nullptr,
                               Nn, DKk, Dd, Dd, Dd, DKk,
                               Hh, (long long)Nn * Dd, 0,
                               Hh, 0, (long long)DKk * Dd,
                               1, (long long)Nn * DKk, 0, 1.0f);
        gemm_tn<<<grid, blk>>>(k_time, w_ks_time, kt, nullptr,
                               Nn, DKk, Dd, Dd, Dd, DKk,
                               Hh, (long long)Nn * Dd, 0,
                               Hh, 0, (long long)DKk * Dd,
                               1, (long long)Nn * DKk, 0, 1.0f);
        gemm_tn<<<grid, blk>>>(q_feature, w_qs_feat, qf, nullptr,
                               Nn, DKk, Dd, Dd, Dd, DKk,
                               Hh, (long long)Nn * Dd, 0,
                               Hh, 0, (long long)DKk * Dd,
                               1, (long long)Nn * DKk, 0, 1.0f);
        gemm_tn<<<grid, blk>>>(k_feature, w_ks_feat, kf, nullptr,
                               Nn, DKk, Dd, Dd, Dd, DKk,
                               Hh, (long long)Nn * Dd, 0,
                               Hh, 0, (long long)DKk * Dd,
                               1, (long long)Nn * DKk, 0, 1.0f);
        gemm_tn<<<grid, blk>>>(v, w_vs, vv, nullptr,
                               Nn, DKk, Dd, Dd, Dd, DKk,
                               Hh, (long long)Nn * Dd, 0,
                               Hh, 0, (long long)DKk * Dd,
                               1, (long long)Nn * DKk, 0, 1.0f);
    }

    float* at = out + AT_OFF;   // attn_time region
    float* af = out + AF_OFF;   // attn_feature region

    // 2) time-attn logits: at[z][n][m] = (1/temp) qt[z][n] . kt[z][m]
    {
        dim3 grid(Nn / BN, Nn / BM, Z), blk(256);
        gemm_tn<<<grid, blk>>>(qt, kt, at, nullptr,
                               Nn, Nn, DKk, DKk, DKk, Nn,
                               1, (long long)Nn * DKk, 0,
                               1, (long long)Nn * DKk, 0,
                               1, (long long)Nn * Nn, 0, inv_temp);
    }
    // 3) masked softmax (in place on d_out attn_time)
    softmax_time_kernel<<<Bz * Hh * Nn, 256>>>(at, attn_mask);

    // 4) feature-attn logits + softmax (in place on d_out attn_feature)
    attnfeat_kernel<<<Z, 256>>>(qf, kf, af, inv_temp);
    softmax_feat_kernel<<<Z * DKk, 128>>>(af);

    // 5) o1 = attn_time @ vv : [N,N]@[N,128]
    {
        dim3 grid(DKk / BN, Nn / BM, Z), blk(256);
        gemm_nn<<<grid, blk>>>(at, vv, o1,
                               Nn, DKk, Nn, Nn, DKk, DKk,
                               1, (long long)Nn * Nn, 0,
                               1, (long long)Nn * DKk, 0,
                               1, (long long)Nn * DKk, 0, 1.0f);
    }

    // 6) prefc[b,n,h*128+e] = o1[z] @ af[z] : [1024,128]@[128,128]
    {
        dim3 grid(DKk / BN, Nn / BM, Z), blk(256);
        gemm_nn<<<grid, blk>>>(o1, af, prefc,
                               Nn, DKk, DKk, DKk, DKk, Dd,
                               1, (long long)Nn * DKk, 0,
                               1, (long long)DKk * DKk, 0,
                               Hh, (long long)Nn * Dd, DKk, 1.0f);
    }

    // 7) preln = prefc @ w_fc^T + v
    {
        dim3 grid(Dd / BN, (Bz * Nn) / BM, 1), blk(256);
        gemm_tn<<<grid, blk>>>(prefc, w_fc, preln, v,
                               Bz * Nn, Dd, Dd, Dd, Dd, Dd,
                               1, 0, 0, 1, 0, 0, 1, 0, 0, 1.0f);
    }

    // 8) LayerNorm -> d_out[0..B*N*D)
    layernorm_kernel<<<Bz * Nn, 256>>>(preln, out, ln_gamma, ln_beta);
}

// round 2
// speedup vs baseline: 5.3950x; 5.3950x over previous
#include <cuda_runtime.h>
#include <math.h>
#include <stdint.h>

// Problem constants
#define Bz   4
#define Nn   1024
#define Dd   1024
#define Hh   8
#define DKk  128
#define EPSf 1e-6f

// d_out layout: [out (B,N,D)] [attn_time (B,H,N,N)] [attn_feature (B,H,DK,DK)]
static const long long AT_OFF  = (long long)Bz * Nn * Dd;                 // 4194304
static const long long AF_OFF  = AT_OFF + (long long)Bz * Hh * Nn * Nn;  // 37748736

// Scratch (device globals; no dynamic allocation allowed)
#define PROJ_ELEMS ((long long)Bz * Hh * Nn * DKk)   // 4194304
__device__ float g_qt[PROJ_ELEMS];
__device__ float g_kt[PROJ_ELEMS];
__device__ float g_qf[PROJ_ELEMS];
__device__ float g_kf[PROJ_ELEMS];
__device__ float g_vv[PROJ_ELEMS];
__device__ float g_o1[PROJ_ELEMS];
__device__ float g_prefc[(long long)Bz * Nn * Dd];
__device__ float g_preln[(long long)Bz * Nn * Dd];

__device__ __forceinline__ long long zoff(int z, int div, long long shi, long long slo) {
    return (long long)(z / div) * shi + (long long)(z % div) * slo;
}

__device__ __forceinline__ uint32_t f2tf32(float x) {
    uint32_t u;
    asm volatile("cvt.rna.tf32.f32 %0, %1;" : "=r"(u) : "f"(x));
    return u;
}

// ---------------------------------------------------------------------------
// TF32 tensor-core GEMM. C = alpha * op(A) * op(B) (+R)
//   AMODE 0: A is [M,K] row-major (lda = K-stride)
//   AMODE 1: A is [K,M] row-major (computes A^T * ...)
//   BMODE 0: B is [N,K] row-major (computes ... * B^T)
//   BMODE 1: B is [K,N] row-major
// Tile: 128x128xBK16, 256 threads = 8 warps (4x2), warp tile 32x64,
// mma.sync.m16n8k8 tf32. All problem dims divisible by tile dims.
// ---------------------------------------------------------------------------
#define TBM 128
#define TBN 128
#define TBK 16

template<int AMODE, int BMODE>
__global__ void __launch_bounds__(256, 2)
mma_gemm(const float* __restrict__ A, const float* __restrict__ B,
         float* __restrict__ C, const float* __restrict__ R,
         int M, int Nc, int K, int lda, int ldb, int ldc,
         int adiv, long long ahi, long long alo,
         int bdiv, long long bhi, long long blo,
         int cdiv, long long chi, long long clo,
         float alpha) {
    __shared__ uint32_t As[TBM][20];    // [m][k], pad->stride 20 (conflict-free frag reads)
    __shared__ uint32_t Bs[TBK][136];   // [k][n], pad->stride 136 (mod 32 == 8)

    const int tid  = threadIdx.x;
    const int lane = tid & 31;
    const int warp = tid >> 5;
    const int warpM = warp >> 1;        // 0..3
    const int warpN = warp & 1;         // 0..1
    const int wm = warpM * 32;
    const int wn = warpN * 64;
    const int g  = lane >> 2;           // group id 0..7
    const int t4 = lane & 3;            // thread in group

    const int row0 = blockIdx.y * TBM;
    const int col0 = blockIdx.x * TBN;
    const int z = blockIdx.z;
    const float* Ab = A + zoff(z, adiv, ahi, alo);
    const float* Bb = B + zoff(z, bdiv, bhi, blo);
    float* Cb = C + zoff(z, cdiv, chi, clo);

    float acc[2][8][4];
    #pragma unroll
    for (int i = 0; i < 2; i++)
        #pragma unroll
        for (int j = 0; j < 8; j++)
            #pragma unroll
            for (int k = 0; k < 4; k++) acc[i][j][k] = 0.f;

    for (int k0 = 0; k0 < K; k0 += TBK) {
        // ---- load A tile -> As[m][k] (tf32) ----
        if (AMODE == 0) {
            #pragma unroll
            for (int it = 0; it < 2; it++) {
                int f = tid + it * 256;            // 512 float4
                int row = f >> 2, c4 = (f & 3) * 4;
                float4 v = *(const float4*)(Ab + (long long)(row0 + row) * lda + k0 + c4);
                uint4 u = make_uint4(f2tf32(v.x), f2tf32(v.y), f2tf32(v.z), f2tf32(v.w));
                *(uint4*)&As[row][c4] = u;
            }
        } else {
            #pragma unroll
            for (int it = 0; it < 2; it++) {
                int f = tid + it * 256;
                int kk2 = f >> 5, m4 = (f & 31) * 4;
                float4 v = *(const float4*)(Ab + (long long)(k0 + kk2) * lda + row0 + m4);
                As[m4 + 0][kk2] = f2tf32(v.x);
                As[m4 + 1][kk2] = f2tf32(v.y);
                As[m4 + 2][kk2] = f2tf32(v.z);
                As[m4 + 3][kk2] = f2tf32(v.w);
            }
        }
        // ---- load B tile -> Bs[k][n] (tf32) ----
        if (BMODE == 0) {
            #pragma unroll
            for (int it = 0; it < 2; it++) {
                int f = tid + it * 256;
                int n = f >> 2, c4 = (f & 3) * 4;
                float4 v = *(const float4*)(Bb + (long long)(col0 + n) * ldb + k0 + c4);
                Bs[c4 + 0][n] = f2tf32(v.x);
                Bs[c4 + 1][n] = f2tf32(v.y);
                Bs[c4 + 2][n] = f2tf32(v.z);
                Bs[c4 + 3][n] = f2tf32(v.w);
            }
        } else {
            #pragma unroll
            for (int it = 0; it < 2; it++) {
                int f = tid + it * 256;
                int kk2 = f >> 5, n4 = (f & 31) * 4;
                float4 v = *(const float4*)(Bb + (long long)(k0 + kk2) * ldb + col0 + n4);
                uint4 u = make_uint4(f2tf32(v.x), f2tf32(v.y), f2tf32(v.z), f2tf32(v.w));
                *(uint4*)&Bs[kk2][n4] = u;
            }
        }
        __syncthreads();

        #pragma unroll
        for (int kk = 0; kk < TBK; kk += 8) {
            uint32_t a[2][4], b[8][2];
            #pragma unroll
            for (int mt = 0; mt < 2; mt++) {
                int mb = wm + mt * 16;
                a[mt][0] = As[mb + g][kk + t4];
                a[mt][1] = As[mb + g + 8][kk + t4];
                a[mt][2] = As[mb + g][kk + t4 + 4];
                a[mt][3] = As[mb + g + 8][kk + t4 + 4];
            }
            #pragma unroll
            for (int nt = 0; nt < 8; nt++) {
                int nb = wn + nt * 8 + g;
                b[nt][0] = Bs[kk + t4][nb];
                b[nt][1] = Bs[kk + t4 + 4][nb];
            }
            #pragma unroll
            for (int mt = 0; mt < 2; mt++)
                #pragma unroll
                for (int nt = 0; nt < 8; nt++) {
                    asm volatile(
                        "mma.sync.aligned.m16n8k8.row.col.f32.tf32.tf32.f32 "
                        "{%0,%1,%2,%3}, {%4,%5,%6,%7}, {%8,%9}, {%0,%1,%2,%3};"
                        : "+f"(acc[mt][nt][0]), "+f"(acc[mt][nt][1]),
                          "+f"(acc[mt][nt][2]), "+f"(acc[mt][nt][3])
                        : "r"(a[mt][0]), "r"(a[mt][1]), "r"(a[mt][2]), "r"(a[mt][3]),
                          "r"(b[nt][0]), "r"(b[nt][1]));
                }
        }
        __syncthreads();
    }

    // ---- epilogue ----
    #pragma unroll
    for (int mt = 0; mt < 2; mt++) {
        int r0g = row0 + wm + mt * 16 + g;
        #pragma unroll
        for (int nt = 0; nt < 8; nt++) {
            int c0g = col0 + wn + nt * 8 + t4 * 2;
            float v0 = acc[mt][nt][0] * alpha;
            float v1 = acc[mt][nt][1] * alpha;
            float v2 = acc[mt][nt][2] * alpha;
            float v3 = acc[mt][nt][3] * alpha;
            if (R) {
                v0 += R[(long long)r0g * ldc + c0g];
                v1 += R[(long long)r0g * ldc + c0g + 1];
                v2 += R[(long long)(r0g + 8) * ldc + c0g];
                v3 += R[(long long)(r0g + 8) * ldc + c0g + 1];
            }
            *(float2*)(Cb + (long long)r0g * ldc + c0g)       = make_float2(v0, v1);
            *(float2*)(Cb + (long long)(r0g + 8) * ldc + c0g) = make_float2(v2, v3);
        }
    }
}

// ---------------------------------------------------------------------------
// Reductions
// ---------------------------------------------------------------------------
__device__ __forceinline__ float block_reduce(float v, bool is_max) {
    __shared__ float sh[32];
    int lane = threadIdx.x & 31, w = threadIdx.x >> 5;
    #pragma unroll
    for (int o = 16; o > 0; o >>= 1) {
        float o2 = __shfl_xor_sync(0xffffffff, v, o);
        v = is_max ? fmaxf(v, o2) : v + o2;
    }
    if (lane == 0) sh[w] = v;
    __syncthreads();
    int nw = (blockDim.x + 31) >> 5;
    v = (lane < nw) ? sh[lane] : (is_max ? -3.4e38f : 0.f);
    if (w == 0) {
        #pragma unroll
        for (int o = 16; o > 0; o >>= 1) {
            float o2 = __shfl_xor_sync(0xffffffff, v, o);
            v = is_max ? fmaxf(v, o2) : v + o2;
        }
        if (lane == 0) sh[0] = v;
    }
    __syncthreads();
    v = sh[0];
    __syncthreads();
    return v;
}

// masked softmax over rows of attn_time (in-place). Row = (b,h,n), 1024 elems, 256 thr.
__global__ void softmax_time_kernel(float* __restrict__ attn, const int* __restrict__ mask) {
    const int r = blockIdx.x;            // b*H*N + h*N + n
    const int b = r / (Hh * Nn);
    const int n = r % Nn;
    float* row = attn + (long long)r * Nn;
    const int* mrow = mask + ((long long)b * Nn + n) * Nn;
    const int t = threadIdx.x;

    float x[4];
    float mx = -3.4e38f;
    #pragma unroll
    for (int i = 0; i < 4; i++) {
        int j = t + i * 256;
        float v = row[j];
        if (mrow[j] == 0) v = -1e9f;
        x[i] = v;
        mx = fmaxf(mx, v);
    }
    mx = block_reduce(mx, true);
    float s = 0.f;
    #pragma unroll
    for (int i = 0; i < 4; i++) { x[i] = __expf(x[i] - mx); s += x[i]; }
    s = block_reduce(s, false);
    float inv = 1.f / s;
    #pragma unroll
    for (int i = 0; i < 4; i++) row[t + i * 256] = x[i] * inv;
}

// softmax over last axis of attn_feature (in-place). Row = 128 elems, 128 thr.
__global__ void softmax_feat_kernel(float* __restrict__ S) {
    float* row = S + (long long)blockIdx.x * DKk;
    float v = row[threadIdx.x];
    float mx = block_reduce(v, true);
    float e = __expf(v - mx);
    float s = block_reduce(e, false);
    row[threadIdx.x] = e / s;
}

// LayerNorm over last dim (1024). 256 thr/row.
__global__ void layernorm_kernel(const float* __restrict__ X, float* __restrict__ O,
                                 const float* __restrict__ gamma, const float* __restrict__ beta) {
    const int r = blockIdx.x;
    const float* row = X + (long long)r * Dd;
    float* orow = O + (long long)r * Dd;
    const int t = threadIdx.x;
    float x[4];
    float s = 0.f, s2 = 0.f;
    #pragma unroll
    for (int i = 0; i < 4; i++) {
        x[i] = row[t + i * 256];
        s += x[i];
        s2 += x[i] * x[i];
    }
    s = block_reduce(s, false);
    s2 = block_reduce(s2, false);
    float mean = s * (1.f / Dd);
    float var = s2 * (1.f / Dd) - mean * mean;
    float inv = rsqrtf(var + EPSf);
    #pragma unroll
    for (int i = 0; i < 4; i++) {
        int j = t + i * 256;
        orow[j] = (x[i] - mean) * inv * gamma[j] + beta[j];
    }
}

// ---------------------------------------------------------------------------
extern "C" void kernel_launch(void* const* d_in, const int* in_sizes, int n_in,
                              void* d_out, int out_size) {
    const float* q_time    = (const float*)d_in[0];
    const float* k_time    = (const float*)d_in[1];
    const float* q_feature = (const float*)d_in[2];
    const float* k_feature = (const float*)d_in[3];
    const float* v         = (const float*)d_in[4];
    const int*   attn_mask = (const int*)  d_in[5];
    const float* w_qs_time = (const float*)d_in[6];
    const float* w_ks_time = (const float*)d_in[7];
    const float* w_qs_feat = (const float*)d_in[8];
    const float* w_ks_feat = (const float*)d_in[9];
    const float* w_vs      = (const float*)d_in[10];
    const float* w_fc      = (const float*)d_in[11];
    const float* ln_gamma  = (const float*)d_in[12];
    const float* ln_beta   = (const float*)d_in[13];
    float* out = (float*)d_out;

    float *qt, *kt, *qf, *kf, *vv, *o1, *prefc, *preln;
    cudaGetSymbolAddress((void**)&qt,    g_qt);
    cudaGetSymbolAddress((void**)&kt,    g_kt);
    cudaGetSymbolAddress((void**)&qf,    g_qf);
    cudaGetSymbolAddress((void**)&kf,    g_kf);
    cudaGetSymbolAddress((void**)&vv,    g_vv);
    cudaGetSymbolAddress((void**)&o1,    g_o1);
    cudaGetSymbolAddress((void**)&prefc, g_prefc);
    cudaGetSymbolAddress((void**)&preln, g_preln);

    const float inv_temp = 1.0f / sqrtf((float)DKk);
    const int Z = Bz * Hh;  // 32
    dim3 blk(256);

    // 1) Projections: per z=(b,h): [1024,128] = X_b[1024,1024] @ W_h[128,1024]^T
    {
        dim3 grid(DKk / TBN, Nn / TBM, Z);
        mma_gemm<0, 0><<<grid, blk>>>(q_time, w_qs_time, qt, nullptr,
                                      Nn, DKk, Dd, Dd, Dd, DKk,
                                      Hh, (long long)Nn * Dd, 0,
                                      Hh, 0, (long long)DKk * Dd,
                                      1, (long long)Nn * DKk, 0, 1.0f);
        mma_gemm<0, 0><<<grid, blk>>>(k_time, w_ks_time, kt, nullptr,
                                      Nn, DKk, Dd, Dd, Dd, DKk,
                                      Hh, (long long)Nn * Dd, 0,
                                      Hh, 0, (long long)DKk * Dd,
                                      1, (long long)Nn * DKk, 0, 1.0f);
        mma_gemm<0, 0><<<grid, blk>>>(q_feature, w_qs_feat, qf, nullptr,
                                      Nn, DKk, Dd, Dd, Dd, DKk,
                                      Hh, (long long)Nn * Dd, 0,
                                      Hh, 0, (long long)DKk * Dd,
                                      1, (long long)Nn * DKk, 0, 1.0f);
        mma_gemm<0, 0><<<grid, blk>>>(k_feature, w_ks_feat, kf, nullptr,
                                      Nn, DKk, Dd, Dd, Dd, DKk,
                                      Hh, (long long)Nn * Dd, 0,
                                      Hh, 0, (long long)DKk * Dd,
                                      1, (long long)Nn * DKk, 0, 1.0f);
        mma_gemm<0, 0><<<grid, blk>>>(v, w_vs, vv, nullptr,
                                      Nn, DKk, Dd, Dd, Dd, DKk,
                                      Hh, (long long)Nn * Dd, 0,
                                      Hh, 0, (long long)DKk * Dd,
                                      1, (long long)Nn * DKk, 0, 1.0f);
    }

    float* at = out + AT_OFF;   // attn_time region
    float* af = out + AF_OFF;   // attn_feature region

    // 2) time-attn logits: at[z] = (1/temp) qt[z] @ kt[z]^T  [1024x1024, K=128]
    {
        dim3 grid(Nn / TBN, Nn / TBM, Z);
        mma_gemm<0, 0><<<grid, blk>>>(qt, kt, at, nullptr,
                                      Nn, Nn, DKk, DKk, DKk, Nn,
                                      1, (long long)Nn * DKk, 0,
                                      1, (long long)Nn * DKk, 0,
                                      1, (long long)Nn * Nn, 0, inv_temp);
    }
    // 3) masked softmax (in place on d_out attn_time)
    softmax_time_kernel<<<Bz * Hh * Nn, 256>>>(at, attn_mask);

    // 4) feature-attn logits: af[z] = (1/temp) qf[z]^T @ kf[z]  [128x128, K=1024]
    {
        dim3 grid(1, 1, Z);
        mma_gemm<1, 1><<<grid, blk>>>(qf, kf, af, nullptr,
                                      DKk, DKk, Nn, DKk, DKk, DKk,
                                      1, (long long)Nn * DKk, 0,
                                      1, (long long)Nn * DKk, 0,
                                      1, (long long)DKk * DKk, 0, inv_temp);
    }
    softmax_feat_kernel<<<Z * DKk, 128>>>(af);

    // 5) o1[z] = at[z] @ vv[z] : [1024,1024]@[1024,128]
    {
        dim3 grid(DKk / TBN, Nn / TBM, Z);
        mma_gemm<0, 1><<<grid, blk>>>(at, vv, o1, nullptr,
                                      Nn, DKk, Nn, Nn, DKk, DKk,
                                      1, (long long)Nn * Nn, 0,
                                      1, (long long)Nn * DKk, 0,
                                      1, (long long)Nn * DKk, 0, 1.0f);
    }

    // 6) prefc[b,n,h*128+e] = o1[z] @ af[z] : [1024,128]@[128,128]
    {
        dim3 grid(DKk / TBN, Nn / TBM, Z);
        mma_gemm<0, 1><<<grid, blk>>>(o1, af, prefc,  nullptr,
                                      Nn, DKk, DKk, DKk, DKk, Dd,
                                      1, (long long)Nn * DKk, 0,
                                      1, (long long)DKk * DKk, 0,
                                      Hh, (long long)Nn * Dd, DKk, 1.0f);
    }

    // 7) preln = prefc @ w_fc^T + v : [4096,1024]@[1024,1024]^T
    {
        dim3 grid(Dd / TBN, (Bz * Nn) / TBM, 1);
        mma_gemm<0, 0><<<grid, blk>>>(prefc, w_fc, preln, v,
                                      Bz * Nn, Dd, Dd, Dd, Dd, Dd,
                                      1, 0, 0, 1, 0, 0, 1, 0, 0, 1.0f);
    }

    // 8) LayerNorm -> d_out[0..B*N*D)
    layernorm_kernel<<<Bz * Nn, 256>>>(preln, out, ln_gamma, ln_beta);
}

// round 3
// speedup vs baseline: 8.0134x; 1.4853x over previous
#include <cuda_runtime.h>
#include <math.h>
#include <stdint.h>

// Problem constants
#define Bz   4
#define Nn   1024
#define Dd   1024
#define Hh   8
#define DKk  128
#define EPSf 1e-6f

static const long long AT_OFF  = (long long)Bz * Nn * Dd;                 // 4194304
static const long long AF_OFF  = AT_OFF + (long long)Bz * Hh * Nn * Nn;  // 37748736

#define PROJ_ELEMS ((long long)Bz * Hh * Nn * DKk)
__device__ float g_qt[PROJ_ELEMS];
__device__ float g_kt[PROJ_ELEMS];
__device__ float g_qf[PROJ_ELEMS];
__device__ float g_kf[PROJ_ELEMS];
__device__ float g_vv[PROJ_ELEMS];
__device__ float g_o1[PROJ_ELEMS];
__device__ float g_prefc[(long long)Bz * Nn * Dd];
__device__ float g_preln[(long long)Bz * Nn * Dd];

__device__ __forceinline__ uint32_t f2tf32(float x) {
    uint32_t u;
    asm volatile("cvt.rna.tf32.f32 %0, %1;" : "=r"(u) : "f"(x));
    return u;
}

__device__ __forceinline__ void cp_async16(float* dst, const float* src) {
    uint32_t s = (uint32_t)__cvta_generic_to_shared(dst);
    asm volatile("cp.async.cg.shared.global [%0], [%1], 16;" :: "r"(s), "l"(src));
}
__device__ __forceinline__ void cp_commit() {
    asm volatile("cp.async.commit_group;" ::: "memory");
}

// ---------------------------------------------------------------------------
// TF32 tensor-core GEMM body, 2-stage cp.async pipeline.
//   AMODE 0: A is [M,K] row-major            AMODE 1: A is [K,M] row-major (A^T)
//   BMODE 0: B is [N,K] row-major (B^T)      BMODE 1: B is [K,N] row-major
// Tile 128x128x16, 256 threads = 8 warps (4x2), warp tile 32x64,
// mma.sync.m16n8k8 tf32. fp32 in smem; cvt->tf32 after LDS.
// smem (2 stages): A<=10240B + B<=10240B per stage -> <=40KB static.
// ---------------------------------------------------------------------------
#define TBM 128
#define TBN 128
#define TBK 16

template<int AMODE, int BMODE>
__device__ __forceinline__ void gemm_body(
    const float* __restrict__ Ab, const float* __restrict__ Bb,
    float* __restrict__ Cb, const float* __restrict__ R,
    int K, int lda, int ldb, int ldc, float alpha,
    int row0, int col0)
{
    constexpr int AS = (AMODE == 0) ? 20 : 136;   // smem row stride (floats)
    constexpr int BS = (BMODE == 0) ? 20 : 136;
    constexpr int ASZ = (AMODE == 0) ? 128 * 20 : 16 * 136;
    constexpr int BSZ = (BMODE == 0) ? 128 * 20 : 16 * 136;

    __shared__ float sA[2][ASZ];
    __shared__ float sB[2][BSZ];

    const int tid  = threadIdx.x;
    const int lane = tid & 31;
    const int warp = tid >> 5;
    const int wm = (warp >> 1) * 32;
    const int wn = (warp & 1) * 64;
    const int g  = lane >> 2;
    const int t4 = lane & 3;

    float acc[2][8][4];
    #pragma unroll
    for (int i = 0; i < 2; i++)
        #pragma unroll
        for (int j = 0; j < 8; j++)
            #pragma unroll
            for (int k = 0; k < 4; k++) acc[i][j][k] = 0.f;

    const int nIter = K / TBK;

    // stage loader: 512 cp.async16 for A + 512 for B (2048 floats each), 256 thr -> 2+2 each
    auto load_stage = [&](int buf, int k0) {
        if (AMODE == 0) {
            #pragma unroll
            for (int it = 0; it < 2; it++) {
                int f = tid + it * 256;
                int row = f >> 2, c4 = (f & 3) * 4;
                cp_async16(&sA[buf][row * AS + c4],
                           Ab + (long long)(row0 + row) * lda + k0 + c4);
            }
        } else {
            #pragma unroll
            for (int it = 0; it < 2; it++) {
                int f = tid + it * 256;
                int k = f >> 5, m4 = (f & 31) * 4;
                cp_async16(&sA[buf][k * AS + m4],
                           Ab + (long long)(k0 + k) * lda + row0 + m4);
            }
        }
        if (BMODE == 0) {
            #pragma unroll
            for (int it = 0; it < 2; it++) {
                int f = tid + it * 256;
                int n = f >> 2, c4 = (f & 3) * 4;
                cp_async16(&sB[buf][n * BS + c4],
                           Bb + (long long)(col0 + n) * ldb + k0 + c4);
            }
        } else {
            #pragma unroll
            for (int it = 0; it < 2; it++) {
                int f = tid + it * 256;
                int k = f >> 5, n4 = (f & 31) * 4;
                cp_async16(&sB[buf][k * BS + n4],
                           Bb + (long long)(k0 + k) * ldb + col0 + n4);
            }
        }
        cp_commit();
    };

    load_stage(0, 0);
    load_stage(1, TBK);

    for (int it = 0; it < nIter; it++) {
        if (it < nIter - 1) asm volatile("cp.async.wait_group 1;" ::: "memory");
        else                asm volatile("cp.async.wait_group 0;" ::: "memory");
        __syncthreads();

        const int cb = it & 1;
        #pragma unroll
        for (int kk = 0; kk < TBK; kk += 8) {
            uint32_t a[2][4], b[8][2];
            #pragma unroll
            for (int mt = 0; mt < 2; mt++) {
                int mb = wm + mt * 16;
                if (AMODE == 0) {
                    a[mt][0] = f2tf32(sA[cb][(mb + g) * AS + kk + t4]);
                    a[mt][1] = f2tf32(sA[cb][(mb + g + 8) * AS + kk + t4]);
                    a[mt][2] = f2tf32(sA[cb][(mb + g) * AS + kk + t4 + 4]);
                    a[mt][3] = f2tf32(sA[cb][(mb + g + 8) * AS + kk + t4 + 4]);
                } else {
                    a[mt][0] = f2tf32(sA[cb][(kk + t4) * AS + mb + g]);
                    a[mt][1] = f2tf32(sA[cb][(kk + t4) * AS + mb + g + 8]);
                    a[mt][2] = f2tf32(sA[cb][(kk + t4 + 4) * AS + mb + g]);
                    a[mt][3] = f2tf32(sA[cb][(kk + t4 + 4) * AS + mb + g + 8]);
                }
            }
            #pragma unroll
            for (int nt = 0; nt < 8; nt++) {
                int nb = wn + nt * 8 + g;
                if (BMODE == 0) {
                    b[nt][0] = f2tf32(sB[cb][nb * BS + kk + t4]);
                    b[nt][1] = f2tf32(sB[cb][nb * BS + kk + t4 + 4]);
                } else {
                    b[nt][0] = f2tf32(sB[cb][(kk + t4) * BS + nb]);
                    b[nt][1] = f2tf32(sB[cb][(kk + t4 + 4) * BS + nb]);
                }
            }
            #pragma unroll
            for (int mt = 0; mt < 2; mt++)
                #pragma unroll
                for (int nt = 0; nt < 8; nt++) {
                    asm volatile(
                        "mma.sync.aligned.m16n8k8.row.col.f32.tf32.tf32.f32 "
                        "{%0,%1,%2,%3}, {%4,%5,%6,%7}, {%8,%9}, {%0,%1,%2,%3};"
                        : "+f"(acc[mt][nt][0]), "+f"(acc[mt][nt][1]),
                          "+f"(acc[mt][nt][2]), "+f"(acc[mt][nt][3])
                        : "r"(a[mt][0]), "r"(a[mt][1]), "r"(a[mt][2]), "r"(a[mt][3]),
                          "r"(b[nt][0]), "r"(b[nt][1]));
                }
        }
        __syncthreads();
        if (it + 2 < nIter) load_stage(cb, (it + 2) * TBK);
    }

    // ---- epilogue ----
    #pragma unroll
    for (int mt = 0; mt < 2; mt++) {
        int r0g = row0 + wm + mt * 16 + g;
        #pragma unroll
        for (int nt = 0; nt < 8; nt++) {
            int c0g = col0 + wn + nt * 8 + t4 * 2;
            float v0 = acc[mt][nt][0] * alpha;
            float v1 = acc[mt][nt][1] * alpha;
            float v2 = acc[mt][nt][2] * alpha;
            float v3 = acc[mt][nt][3] * alpha;
            if (R) {
                v0 += R[(long long)r0g * ldc + c0g];
                v1 += R[(long long)r0g * ldc + c0g + 1];
                v2 += R[(long long)(r0g + 8) * ldc + c0g];
                v3 += R[(long long)(r0g + 8) * ldc + c0g + 1];
            }
            *(float2*)(Cb + (long long)r0g * ldc + c0g)       = make_float2(v0, v1);
            *(float2*)(Cb + (long long)(r0g + 8) * ldc + c0g) = make_float2(v2, v3);
        }
    }
}

__device__ __forceinline__ long long zoff(int z, int div, long long shi, long long slo) {
    return (long long)(z / div) * shi + (long long)(z % div) * slo;
}

template<int AMODE, int BMODE>
__global__ void __launch_bounds__(256, 2)
mma_gemm(const float* __restrict__ A, const float* __restrict__ B,
         float* __restrict__ C, const float* __restrict__ R,
         int K, int lda, int ldb, int ldc,
         int adiv, long long ahi, long long alo,
         int bdiv, long long bhi, long long blo,
         int cdiv, long long chi, long long clo,
         float alpha) {
    const int z = blockIdx.z;
    gemm_body<AMODE, BMODE>(A + zoff(z, adiv, ahi, alo),
                            B + zoff(z, bdiv, bhi, blo),
                            C + zoff(z, cdiv, chi, clo), R,
                            K, lda, ldb, ldc, alpha,
                            blockIdx.y * TBM, blockIdx.x * TBN);
}

// All 5 projections in one launch. z in [0,160): p = z/32 selects (X,W,C), zz = z%32 = (b,h).
__global__ void __launch_bounds__(256, 2)
proj_gemm(const float* x0, const float* x1, const float* x2, const float* x3, const float* x4,
          const float* w0, const float* w1, const float* w2, const float* w3, const float* w4,
          float* c0, float* c1, float* c2, float* c3, float* c4) {
    const int z = blockIdx.z;
    const int p = z >> 5, zz = z & 31;
    const float* X; const float* W; float* C;
    switch (p) {
        case 0: X = x0; W = w0; C = c0; break;
        case 1: X = x1; W = w1; C = c1; break;
        case 2: X = x2; W = w2; C = c2; break;
        case 3: X = x3; W = w3; C = c3; break;
        default: X = x4; W = w4; C = c4; break;
    }
    const float* Ab = X + (long long)(zz >> 3) * Nn * Dd;     // batch
    const float* Bb = W + (long long)(zz & 7) * DKk * Dd;     // head block of W
    float* Cb = C + (long long)zz * Nn * DKk;
    gemm_body<0, 0>(Ab, Bb, Cb, nullptr, Dd, Dd, Dd, DKk, 1.0f,
                    blockIdx.y * TBM, blockIdx.x * TBN);
}

// ---------------------------------------------------------------------------
// Reductions
// ---------------------------------------------------------------------------
__device__ __forceinline__ float block_reduce(float v, bool is_max) {
    __shared__ float sh[32];
    int lane = threadIdx.x & 31, w = threadIdx.x >> 5;
    #pragma unroll
    for (int o = 16; o > 0; o >>= 1) {
        float o2 = __shfl_xor_sync(0xffffffff, v, o);
        v = is_max ? fmaxf(v, o2) : v + o2;
    }
    if (lane == 0) sh[w] = v;
    __syncthreads();
    int nw = (blockDim.x + 31) >> 5;
    v = (lane < nw) ? sh[lane] : (is_max ? -3.4e38f : 0.f);
    if (w == 0) {
        #pragma unroll
        for (int o = 16; o > 0; o >>= 1) {
            float o2 = __shfl_xor_sync(0xffffffff, v, o);
            v = is_max ? fmaxf(v, o2) : v + o2;
        }
        if (lane == 0) sh[0] = v;
    }
    __syncthreads();
    v = sh[0];
    __syncthreads();
    return v;
}

__global__ void softmax_time_kernel(float* __restrict__ attn, const int* __restrict__ mask) {
    const int r = blockIdx.x;
    const int b = r / (Hh * Nn);
    const int n = r % Nn;
    float* row = attn + (long long)r * Nn;
    const int* mrow = mask + ((long long)b * Nn + n) * Nn;
    const int t = threadIdx.x;

    float x[4];
    float mx = -3.4e38f;
    #pragma unroll
    for (int i = 0; i < 4; i++) {
        int j = t + i * 256;
        float v = row[j];
        if (mrow[j] == 0) v = -1e9f;
        x[i] = v;
        mx = fmaxf(mx, v);
    }
    mx = block_reduce(mx, true);
    float s = 0.f;
    #pragma unroll
    for (int i = 0; i < 4; i++) { x[i] = __expf(x[i] - mx); s += x[i]; }
    s = block_reduce(s, false);
    float inv = 1.f / s;
    #pragma unroll
    for (int i = 0; i < 4; i++) row[t + i * 256] = x[i] * inv;
}

__global__ void softmax_feat_kernel(float* __restrict__ S) {
    float* row = S + (long long)blockIdx.x * DKk;
    float v = row[threadIdx.x];
    float mx = block_reduce(v, true);
    float e = __expf(v - mx);
    float s = block_reduce(e, false);
    row[threadIdx.x] = e / s;
}

__global__ void layernorm_kernel(const float* __restrict__ X, float* __restrict__ O,
                                 const float* __restrict__ gamma, const float* __restrict__ beta) {
    const int r = blockIdx.x;
    const float* row = X + (long long)r * Dd;
    float* orow = O + (long long)r * Dd;
    const int t = threadIdx.x;
    float x[4];
    float s = 0.f, s2 = 0.f;
    #pragma unroll
    for (int i = 0; i < 4; i++) {
        x[i] = row[t + i * 256];
        s += x[i];
        s2 += x[i] * x[i];
    }
    s = block_reduce(s, false);
    s2 = block_reduce(s2, false);
    float mean = s * (1.f / Dd);
    float var = s2 * (1.f / Dd) - mean * mean;
    float inv = rsqrtf(var + EPSf);
    #pragma unroll
    for (int i = 0; i < 4; i++) {
        int j = t + i * 256;
        orow[j] = (x[i] - mean) * inv * gamma[j] + beta[j];
    }
}

// ---------------------------------------------------------------------------
extern "C" void kernel_launch(void* const* d_in, const int* in_sizes, int n_in,
                              void* d_out, int out_size) {
    const float* q_time    = (const float*)d_in[0];
    const float* k_time    = (const float*)d_in[1];
    const float* q_feature = (const float*)d_in[2];
    const float* k_feature = (const float*)d_in[3];
    const float* v         = (const float*)d_in[4];
    const int*   attn_mask = (const int*)  d_in[5];
    const float* w_qs_time = (const float*)d_in[6];
    const float* w_ks_time = (const float*)d_in[7];
    const float* w_qs_feat = (const float*)d_in[8];
    const float* w_ks_feat = (const float*)d_in[9];
    const float* w_vs      = (const float*)d_in[10];
    const float* w_fc      = (const float*)d_in[11];
    const float* ln_gamma  = (const float*)d_in[12];
    const float* ln_beta   = (const float*)d_in[13];
    float* out = (float*)d_out;

    float *qt, *kt, *qf, *kf, *vv, *o1, *prefc, *preln;
    cudaGetSymbolAddress((void**)&qt,    g_qt);
    cudaGetSymbolAddress((void**)&kt,    g_kt);
    cudaGetSymbolAddress((void**)&qf,    g_qf);
    cudaGetSymbolAddress((void**)&kf,    g_kf);
    cudaGetSymbolAddress((void**)&vv,    g_vv);
    cudaGetSymbolAddress((void**)&o1,    g_o1);
    cudaGetSymbolAddress((void**)&prefc, g_prefc);
    cudaGetSymbolAddress((void**)&preln, g_preln);

    const float inv_temp = 1.0f / sqrtf((float)DKk);
    const int Z = Bz * Hh;  // 32
    dim3 blk(256);

    // 1) All projections in one launch: grid.z = 5*32
    {
        dim3 grid(1, Nn / TBM, 5 * Z);
        proj_gemm<<<grid, blk>>>(q_time, k_time, q_feature, k_feature, v,
                                 w_qs_time, w_ks_time, w_qs_feat, w_ks_feat, w_vs,
                                 qt, kt, qf, kf, vv);
    }

    float* at = out + AT_OFF;
    float* af = out + AF_OFF;

    // 2) time-attn logits: at[z] = (1/temp) qt[z] @ kt[z]^T  [1024x1024, K=128]
    {
        dim3 grid(Nn / TBN, Nn / TBM, Z);
        mma_gemm<0, 0><<<grid, blk>>>(qt, kt, at, nullptr,
                                      DKk, DKk, DKk, Nn,
                                      1, (long long)Nn * DKk, 0,
                                      1, (long long)Nn * DKk, 0,
                                      1, (long long)Nn * Nn, 0, inv_temp);
    }
    softmax_time_kernel<<<Bz * Hh * Nn, 256>>>(at, attn_mask);

    // 4) feature-attn logits: af[z] = (1/temp) qf[z]^T @ kf[z]  [128x128, K=1024]
    {
        dim3 grid(1, 1, Z);
        mma_gemm<1, 1><<<grid, blk>>>(qf, kf, af, nullptr,
                                      Nn, DKk, DKk, DKk,
                                      1, (long long)Nn * DKk, 0,
                                      1, (long long)Nn * DKk, 0,
                                      1, (long long)DKk * DKk, 0, inv_temp);
    }
    softmax_feat_kernel<<<Z * DKk, 128>>>(af);

    // 5) o1[z] = at[z] @ vv[z] : [1024,1024]@[1024,128]
    {
        dim3 grid(1, Nn / TBM, Z);
        mma_gemm<0, 1><<<grid, blk>>>(at, vv, o1, nullptr,
                                      Nn, Nn, DKk, DKk,
                                      1, (long long)Nn * Nn, 0,
                                      1, (long long)Nn * DKk, 0,
                                      1, (long long)Nn * DKk, 0, 1.0f);
    }

    // 6) prefc[b,n,h*128+e] = o1[z] @ af[z] : [1024,128]@[128,128]
    {
        dim3 grid(1, Nn / TBM, Z);
        mma_gemm<0, 1><<<grid, blk>>>(o1, af, prefc, nullptr,
                                      DKk, DKk, DKk, Dd,
                                      1, (long long)Nn * DKk, 0,
                                      1, (long long)DKk * DKk, 0,
                                      Hh, (long long)Nn * Dd, DKk, 1.0f);
    }

    // 7) preln = prefc @ w_fc^T + v : [4096,1024]@[1024,1024]^T
    {
        dim3 grid(Dd / TBN, (Bz * Nn) / TBM, 1);
        mma_gemm<0, 0><<<grid, blk>>>(prefc, w_fc, preln, v,
                                      Dd, Dd, Dd, Dd,
                                      1, 0, 0, 1, 0, 0, 1, 0, 0, 1.0f);
    }

    // 8) LayerNorm
    layernorm_kernel<<<Bz * Nn, 256>>>(preln, out, ln_gamma, ln_beta);
}

// round 4
// speedup vs baseline: 8.4599x; 1.0557x over previous
#include <cuda_runtime.h>
#include <math.h>
#include <stdint.h>

// Problem constants
#define Bz   4
#define Nn   1024
#define Dd   1024
#define Hh   8
#define DKk  128
#define EPSf 1e-6f

static const long long AT_OFF  = (long long)Bz * Nn * Dd;                 // 4194304
static const long long AF_OFF  = AT_OFF + (long long)Bz * Hh * Nn * Nn;  // 37748736

#define PROJ_ELEMS ((long long)Bz * Hh * Nn * DKk)
__device__ float g_qt[PROJ_ELEMS];
__device__ float g_kt[PROJ_ELEMS];
__device__ float g_qf[PROJ_ELEMS];
__device__ float g_kf[PROJ_ELEMS];
__device__ float g_vv[PROJ_ELEMS];
__device__ float g_o1[PROJ_ELEMS];
__device__ float g_prefc[(long long)Bz * Nn * Dd];
__device__ float g_preln[(long long)Bz * Nn * Dd];
__device__ float g_afp[(long long)32 * 8 * DKk * DKk];   // split-K partials (16 MB)

__device__ __forceinline__ uint32_t f2tf32(float x) {
    uint32_t u;
    asm volatile("cvt.rna.tf32.f32 %0, %1;" : "=r"(u) : "f"(x));
    return u;
}
__device__ __forceinline__ void cp_async16(float* dst, const float* src) {
    uint32_t s = (uint32_t)__cvta_generic_to_shared(dst);
    asm volatile("cp.async.cg.shared.global [%0], [%1], 16;" :: "r"(s), "l"(src));
}
__device__ __forceinline__ void cp_commit() {
    asm volatile("cp.async.commit_group;" ::: "memory");
}

// ---------------------------------------------------------------------------
// TF32 tensor-core GEMM body, 3-stage cp.async pipeline, dynamic smem.
//   AMODE 0: A [M,K] rm          AMODE 1: A [K,M] rm (A^T)
//   BMODE 0: B [N,K] rm (B^T)    BMODE 1: B [K,N] rm
// Tile 128x128x16, 256 thr = 8 warps (4x2), warp tile 32x64, mma m16n8k8 tf32.
// Dynamic smem: 3 * (2560 + 2560) floats = 61440 B (worst case layout).
// ---------------------------------------------------------------------------
#define TBM 128
#define TBN 128
#define TBK 16
#define NST 3
#define SMEM_BYTES (NST * (2560 + 2560) * 4)

template<int AMODE, int BMODE>
__device__ __forceinline__ void gemm_body(
    float* __restrict__ smem,
    const float* __restrict__ Ab, const float* __restrict__ Bb,
    float* __restrict__ Cb, const float* __restrict__ R,
    int K, int lda, int ldb, int ldc, float alpha,
    int row0, int col0)
{
    constexpr int AS = (AMODE == 0) ? 20 : 136;
    constexpr int BS = (BMODE == 0) ? 20 : 136;
    constexpr int ASZ = (AMODE == 0) ? 128 * 20 : 16 * 136;
    constexpr int BSZ = (BMODE == 0) ? 128 * 20 : 16 * 136;

    float* sA = smem;              // [NST][ASZ]
    float* sB = smem + NST * ASZ;  // [NST][BSZ]

    const int tid  = threadIdx.x;
    const int lane = tid & 31;
    const int warp = tid >> 5;
    const int wm = (warp >> 1) * 32;
    const int wn = (warp & 1) * 64;
    const int g  = lane >> 2;
    const int t4 = lane & 3;

    float acc[2][8][4];
    #pragma unroll
    for (int i = 0; i < 2; i++)
        #pragma unroll
        for (int j = 0; j < 8; j++)
            #pragma unroll
            for (int k = 0; k < 4; k++) acc[i][j][k] = 0.f;

    const int nIter = K / TBK;

    auto load_stage = [&](int buf, int k0) {
        float* dA = sA + buf * ASZ;
        float* dB = sB + buf * BSZ;
        if (AMODE == 0) {
            #pragma unroll
            for (int it = 0; it < 2; it++) {
                int f = tid + it * 256;
                int row = f >> 2, c4 = (f & 3) * 4;
                cp_async16(&dA[row * AS + c4],
                           Ab + (long long)(row0 + row) * lda + k0 + c4);
            }
        } else {
            #pragma unroll
            for (int it = 0; it < 2; it++) {
                int f = tid + it * 256;
                int k = f >> 5, m4 = (f & 31) * 4;
                cp_async16(&dA[k * AS + m4],
                           Ab + (long long)(k0 + k) * lda + row0 + m4);
            }
        }
        if (BMODE == 0) {
            #pragma unroll
            for (int it = 0; it < 2; it++) {
                int f = tid + it * 256;
                int n = f >> 2, c4 = (f & 3) * 4;
                cp_async16(&dB[n * BS + c4],
                           Bb + (long long)(col0 + n) * ldb + k0 + c4);
            }
        } else {
            #pragma unroll
            for (int it = 0; it < 2; it++) {
                int f = tid + it * 256;
                int k = f >> 5, n4 = (f & 31) * 4;
                cp_async16(&dB[k * BS + n4],
                           Bb + (long long)(k0 + k) * ldb + col0 + n4);
            }
        }
        cp_commit();
    };

    // prologue: fill 3 stages (all our K >= 128 so nIter >= 8)
    load_stage(0, 0);
    load_stage(1, TBK);
    load_stage(2, 2 * TBK);

    for (int it = 0; it < nIter; it++) {
        const int rem = nIter - 1 - it;
        if (rem >= 2)      asm volatile("cp.async.wait_group 2;" ::: "memory");
        else if (rem == 1) asm volatile("cp.async.wait_group 1;" ::: "memory");
        else               asm volatile("cp.async.wait_group 0;" ::: "memory");
        __syncthreads();

        const int cb = it % NST;
        const float* cA = sA + cb * ASZ;
        const float* cB = sB + cb * BSZ;
        #pragma unroll
        for (int kk = 0; kk < TBK; kk += 8) {
            uint32_t a[2][4], b[8][2];
            #pragma unroll
            for (int mt = 0; mt < 2; mt++) {
                int mb = wm + mt * 16;
                if (AMODE == 0) {
                    a[mt][0] = f2tf32(cA[(mb + g) * AS + kk + t4]);
                    a[mt][1] = f2tf32(cA[(mb + g + 8) * AS + kk + t4]);
                    a[mt][2] = f2tf32(cA[(mb + g) * AS + kk + t4 + 4]);
                    a[mt][3] = f2tf32(cA[(mb + g + 8) * AS + kk + t4 + 4]);
                } else {
                    a[mt][0] = f2tf32(cA[(kk + t4) * AS + mb + g]);
                    a[mt][1] = f2tf32(cA[(kk + t4) * AS + mb + g + 8]);
                    a[mt][2] = f2tf32(cA[(kk + t4 + 4) * AS + mb + g]);
                    a[mt][3] = f2tf32(cA[(kk + t4 + 4) * AS + mb + g + 8]);
                }
            }
            #pragma unroll
            for (int nt = 0; nt < 8; nt++) {
                int nb = wn + nt * 8 + g;
                if (BMODE == 0) {
                    b[nt][0] = f2tf32(cB[nb * BS + kk + t4]);
                    b[nt][1] = f2tf32(cB[nb * BS + kk + t4 + 4]);
                } else {
                    b[nt][0] = f2tf32(cB[(kk + t4) * BS + nb]);
                    b[nt][1] = f2tf32(cB[(kk + t4 + 4) * BS + nb]);
                }
            }
            #pragma unroll
            for (int mt = 0; mt < 2; mt++)
                #pragma unroll
                for (int nt = 0; nt < 8; nt++) {
                    asm volatile(
                        "mma.sync.aligned.m16n8k8.row.col.f32.tf32.tf32.f32 "
                        "{%0,%1,%2,%3}, {%4,%5,%6,%7}, {%8,%9}, {%0,%1,%2,%3};"
                        : "+f"(acc[mt][nt][0]), "+f"(acc[mt][nt][1]),
                          "+f"(acc[mt][nt][2]), "+f"(acc[mt][nt][3])
                        : "r"(a[mt][0]), "r"(a[mt][1]), "r"(a[mt][2]), "r"(a[mt][3]),
                          "r"(b[nt][0]), "r"(b[nt][1]));
                }
        }
        __syncthreads();
        if (it + NST < nIter) load_stage(cb, (it + NST) * TBK);
    }

    #pragma unroll
    for (int mt = 0; mt < 2; mt++) {
        int r0g = row0 + wm + mt * 16 + g;
        #pragma unroll
        for (int nt = 0; nt < 8; nt++) {
            int c0g = col0 + wn + nt * 8 + t4 * 2;
            float v0 = acc[mt][nt][0] * alpha;
            float v1 = acc[mt][nt][1] * alpha;
            float v2 = acc[mt][nt][2] * alpha;
            float v3 = acc[mt][nt][3] * alpha;
            if (R) {
                v0 += R[(long long)r0g * ldc + c0g];
                v1 += R[(long long)r0g * ldc + c0g + 1];
                v2 += R[(long long)(r0g + 8) * ldc + c0g];
                v3 += R[(long long)(r0g + 8) * ldc + c0g + 1];
            }
            *(float2*)(Cb + (long long)r0g * ldc + c0g)       = make_float2(v0, v1);
            *(float2*)(Cb + (long long)(r0g + 8) * ldc + c0g) = make_float2(v2, v3);
        }
    }
}

__device__ __forceinline__ long long zoff(int z, int div, long long shi, long long slo) {
    return (long long)(z / div) * shi + (long long)(z % div) * slo;
}

template<int AMODE, int BMODE>
__global__ void __launch_bounds__(256, 2)
mma_gemm(const float* __restrict__ A, const float* __restrict__ B,
         float* __restrict__ C, const float* __restrict__ R,
         int K, int lda, int ldb, int ldc,
         int adiv, long long ahi, long long alo,
         int bdiv, long long bhi, long long blo,
         int cdiv, long long chi, long long clo,
         float alpha) {
    extern __shared__ float dynsmem[];
    const int z = blockIdx.z;
    gemm_body<AMODE, BMODE>(dynsmem,
                            A + zoff(z, adiv, ahi, alo),
                            B + zoff(z, bdiv, bhi, blo),
                            C + zoff(z, cdiv, chi, clo), R,
                            K, lda, ldb, ldc, alpha,
                            blockIdx.y * TBM, blockIdx.x * TBN);
}

// All 5 projections in one launch. z in [0,160): p = z/32, zz = z%32 = (b,h).
__global__ void __launch_bounds__(256, 2)
proj_gemm(const float* x0, const float* x1, const float* x2, const float* x3, const float* x4,
          const float* w0, const float* w1, const float* w2, const float* w3, const float* w4,
          float* c0, float* c1, float* c2, float* c3, float* c4) {
    extern __shared__ float dynsmem[];
    const int z = blockIdx.z;
    const int p = z >> 5, zz = z & 31;
    const float* X; const float* W; float* C;
    switch (p) {
        case 0: X = x0; W = w0; C = c0; break;
        case 1: X = x1; W = w1; C = c1; break;
        case 2: X = x2; W = w2; C = c2; break;
        case 3: X = x3; W = w3; C = c3; break;
        default: X = x4; W = w4; C = c4; break;
    }
    gemm_body<0, 0>(dynsmem,
                    X + (long long)(zz >> 3) * Nn * Dd,
                    W + (long long)(zz & 7) * DKk * Dd,
                    C + (long long)zz * Nn * DKk, nullptr,
                    Dd, Dd, Dd, DKk, 1.0f, blockIdx.y * TBM, 0);
}

// Merged: time-attn logits (2048 tiles) + feature-attn split-K partials (256 tiles).
__global__ void __launch_bounds__(256, 2)
fused_logits(const float* __restrict__ qt, const float* __restrict__ kt,
             const float* __restrict__ qf, const float* __restrict__ kf,
             float* __restrict__ at, float* __restrict__ afp, float alpha) {
    extern __shared__ float dynsmem[];
    const int bx = blockIdx.x;
    if (bx < 2048) {
        const int z = bx >> 6, rem = bx & 63;
        gemm_body<0, 0>(dynsmem,
                        qt + (long long)z * Nn * DKk,
                        kt + (long long)z * Nn * DKk,
                        at + (long long)z * Nn * Nn, nullptr,
                        DKk, DKk, DKk, Nn, alpha,
                        (rem >> 3) * TBM, (rem & 7) * TBN);
    } else {
        const int e = bx - 2048;           // 0..255: z*8 + sub
        const int z = e >> 3, sub = e & 7;
        const long long base = (long long)z * Nn * DKk + (long long)sub * 128 * DKk;
        gemm_body<1, 1>(dynsmem,
                        qf + base, kf + base,
                        afp + (long long)e * DKk * DKk, nullptr,
                        128, DKk, DKk, DKk, alpha, 0, 0);
    }
}

// ---------------------------------------------------------------------------
__device__ __forceinline__ float block_reduce(float v, bool is_max) {
    __shared__ float sh[32];
    int lane = threadIdx.x & 31, w = threadIdx.x >> 5;
    #pragma unroll
    for (int o = 16; o > 0; o >>= 1) {
        float o2 = __shfl_xor_sync(0xffffffff, v, o);
        v = is_max ? fmaxf(v, o2) : v + o2;
    }
    if (lane == 0) sh[w] = v;
    __syncthreads();
    int nw = (blockDim.x + 31) >> 5;
    v = (lane < nw) ? sh[lane] : (is_max ? -3.4e38f : 0.f);
    if (w == 0) {
        #pragma unroll
        for (int o = 16; o > 0; o >>= 1) {
            float o2 = __shfl_xor_sync(0xffffffff, v, o);
            v = is_max ? fmaxf(v, o2) : v + o2;
        }
        if (lane == 0) sh[0] = v;
    }
    __syncthreads();
    v = sh[0];
    __syncthreads();
    return v;
}

__global__ void softmax_time_kernel(float* __restrict__ attn, const int* __restrict__ mask) {
    const int r = blockIdx.x;
    const int b = r / (Hh * Nn);
    const int n = r % Nn;
    float* row = attn + (long long)r * Nn;
    const int* mrow = mask + ((long long)b * Nn + n) * Nn;
    const int t = threadIdx.x;

    float x[4];
    float mx = -3.4e38f;
    #pragma unroll
    for (int i = 0; i < 4; i++) {
        int j = t + i * 256;
        float v = row[j];
        if (mrow[j] == 0) v = -1e9f;
        x[i] = v;
        mx = fmaxf(mx, v);
    }
    mx = block_reduce(mx, true);
    float s = 0.f;
    #pragma unroll
    for (int i = 0; i < 4; i++) { x[i] = __expf(x[i] - mx); s += x[i]; }
    s = block_reduce(s, false);
    float inv = 1.f / s;
    #pragma unroll
    for (int i = 0; i < 4; i++) row[t + i * 256] = x[i] * inv;
}

// reduce 8 split-K partials + softmax over last axis. block = (z,row), 128 thr.
__global__ void softmax_feat_kernel(const float* __restrict__ afp, float* __restrict__ S) {
    const int z = blockIdx.x >> 7;
    const int row = blockIdx.x & 127;
    const int t = threadIdx.x;
    float v = 0.f;
    #pragma unroll
    for (int s8 = 0; s8 < 8; s8++)
        v += afp[(((long long)z * 8 + s8) * DKk + row) * DKk + t];
    float mx = block_reduce(v, true);
    float e = __expf(v - mx);
    float s = block_reduce(e, false);
    S[((long long)z * DKk + row) * DKk + t] = e / s;
}

__global__ void layernorm_kernel(const float* __restrict__ X, float* __restrict__ O,
                                 const float* __restrict__ gamma, const float* __restrict__ beta) {
    const int r = blockIdx.x;
    const float* row = X + (long long)r * Dd;
    float* orow = O + (long long)r * Dd;
    const int t = threadIdx.x;
    float x[4];
    float s = 0.f, s2 = 0.f;
    #pragma unroll
    for (int i = 0; i < 4; i++) {
        x[i] = row[t + i * 256];
        s += x[i];
        s2 += x[i] * x[i];
    }
    s = block_reduce(s, false);
    s2 = block_reduce(s2, false);
    float mean = s * (1.f / Dd);
    float var = s2 * (1.f / Dd) - mean * mean;
    float inv = rsqrtf(var + EPSf);
    #pragma unroll
    for (int i = 0; i < 4; i++) {
        int j = t + i * 256;
        orow[j] = (x[i] - mean) * inv * gamma[j] + beta[j];
    }
}

// ---------------------------------------------------------------------------
extern "C" void kernel_launch(void* const* d_in, const int* in_sizes, int n_in,
                              void* d_out, int out_size) {
    const float* q_time    = (const float*)d_in[0];
    const float* k_time    = (const float*)d_in[1];
    const float* q_feature = (const float*)d_in[2];
    const float* k_feature = (const float*)d_in[3];
    const float* v         = (const float*)d_in[4];
    const int*   attn_mask = (const int*)  d_in[5];
    const float* w_qs_time = (const float*)d_in[6];
    const float* w_ks_time = (const float*)d_in[7];
    const float* w_qs_feat = (const float*)d_in[8];
    const float* w_ks_feat = (const float*)d_in[9];
    const float* w_vs      = (const float*)d_in[10];
    const float* w_fc      = (const float*)d_in[11];
    const float* ln_gamma  = (const float*)d_in[12];
    const float* ln_beta   = (const float*)d_in[13];
    float* out = (float*)d_out;

    float *qt, *kt, *qf, *kf, *vv, *o1, *prefc, *preln, *afp;
    cudaGetSymbolAddress((void**)&qt,    g_qt);
    cudaGetSymbolAddress((void**)&kt,    g_kt);
    cudaGetSymbolAddress((void**)&qf,    g_qf);
    cudaGetSymbolAddress((void**)&kf,    g_kf);
    cudaGetSymbolAddress((void**)&vv,    g_vv);
    cudaGetSymbolAddress((void**)&o1,    g_o1);
    cudaGetSymbolAddress((void**)&prefc, g_prefc);
    cudaGetSymbolAddress((void**)&preln, g_preln);
    cudaGetSymbolAddress((void**)&afp,   g_afp);

    // opt-in to >48KB dynamic smem (idempotent, host-side)
    cudaFuncSetAttribute(proj_gemm, cudaFuncAttributeMaxDynamicSharedMemorySize, SMEM_BYTES);
    cudaFuncSetAttribute(fused_logits, cudaFuncAttributeMaxDynamicSharedMemorySize, SMEM_BYTES);
    cudaFuncSetAttribute(mma_gemm<0, 0>, cudaFuncAttributeMaxDynamicSharedMemorySize, SMEM_BYTES);
    cudaFuncSetAttribute(mma_gemm<0, 1>, cudaFuncAttributeMaxDynamicSharedMemorySize, SMEM_BYTES);

    const float inv_temp = 1.0f / sqrtf((float)DKk);
    const int Z = Bz * Hh;  // 32
    dim3 blk(256);

    // 1) all projections, one launch
    {
        dim3 grid(1, Nn / TBM, 5 * Z);
        proj_gemm<<<grid, blk, SMEM_BYTES>>>(q_time, k_time, q_feature, k_feature, v,
                                             w_qs_time, w_ks_time, w_qs_feat, w_ks_feat, w_vs,
                                             qt, kt, qf, kf, vv);
    }

    float* at = out + AT_OFF;
    float* af = out + AF_OFF;

    // 2) time logits + feature split-K partials, one launch
    fused_logits<<<2048 + 256, blk, SMEM_BYTES>>>(qt, kt, qf, kf, at, afp, inv_temp);

    // 3) softmaxes (independent)
    softmax_time_kernel<<<Bz * Hh * Nn, 256>>>(at, attn_mask);
    softmax_feat_kernel<<<Z * DKk, 128>>>(afp, af);

    // 4) o1[z] = at[z] @ vv[z] : [1024,1024]@[1024,128]
    {
        dim3 grid(1, Nn / TBM, Z);
        mma_gemm<0, 1><<<grid, blk, SMEM_BYTES>>>(at, vv, o1, nullptr,
                                      Nn, Nn, DKk, DKk,
                                      1, (long long)Nn * Nn, 0,
                                      1, (long long)Nn * DKk, 0,
                                      1, (long long)Nn * DKk, 0, 1.0f);
    }

    // 5) prefc[b,n,h*128+e] = o1[z] @ af[z]
    {
        dim3 grid(1, Nn / TBM, Z);
        mma_gemm<0, 1><<<grid, blk, SMEM_BYTES>>>(o1, af, prefc, nullptr,
                                      DKk, DKk, DKk, Dd,
                                      1, (long long)Nn * DKk, 0,
                                      1, (long long)DKk * DKk, 0,
                                      Hh, (long long)Nn * Dd, DKk, 1.0f);
    }

    // 6) preln = prefc @ w_fc^T + v
    {
        dim3 grid(Dd / TBN, (Bz * Nn) / TBM, 1);
        mma_gemm<0, 0><<<grid, blk, SMEM_BYTES>>>(prefc, w_fc, preln, v,
                                      Dd, Dd, Dd, Dd,
                                      1, 0, 0, 1, 0, 0, 1, 0, 0, 1.0f);
    }

    // 7) LayerNorm
    layernorm_kernel<<<Bz * Nn, 256>>>(preln, out, ln_gamma, ln_beta);
}

// round 5
// speedup vs baseline: 9.4185x; 1.1133x over previous
#include <cuda_runtime.h>
#include <math.h>
#include <stdint.h>

// Problem constants
#define Bz   4
#define Nn   1024
#define Dd   1024
#define Hh   8
#define DKk  128
#define EPSf 1e-6f

static const long long AT_OFF  = (long long)Bz * Nn * Dd;                 // 4194304
static const long long AF_OFF  = AT_OFF + (long long)Bz * Hh * Nn * Nn;  // 37748736

#define PROJ_ELEMS ((long long)Bz * Hh * Nn * DKk)
__device__ float g_qt[PROJ_ELEMS];
__device__ float g_kt[PROJ_ELEMS];
__device__ float g_qf[PROJ_ELEMS];
__device__ float g_kf[PROJ_ELEMS];
__device__ float g_vv[PROJ_ELEMS];
__device__ float g_o1[PROJ_ELEMS];
__device__ float g_prefc[(long long)Bz * Nn * Dd];
__device__ float g_preln[(long long)Bz * Nn * Dd];
__device__ float g_afp[(long long)32 * 8 * DKk * DKk];   // split-K partials
__device__ float g_w[6u * 1048576u];                      // tf32-rounded weights

__device__ __forceinline__ uint32_t f2tf32(float x) {
    uint32_t u;
    asm volatile("cvt.rna.tf32.f32 %0, %1;" : "=r"(u) : "f"(x));
    return u;
}
__device__ __forceinline__ void cp_async16(float* dst, const float* src) {
    uint32_t s = (uint32_t)__cvta_generic_to_shared(dst);
    asm volatile("cp.async.cg.shared.global [%0], [%1], 16;" :: "r"(s), "l"(src));
}
__device__ __forceinline__ void cp_commit() {
    asm volatile("cp.async.commit_group;" ::: "memory");
}

// Pre-round the 6 weight matrices (1M floats each) to tf32-representable fp32.
__global__ void round_w_kernel(const float* w0, const float* w1, const float* w2,
                               const float* w3, const float* w4, const float* w5,
                               float* dst) {
    const int b = blockIdx.x;                 // 0..6143
    const int t = b >> 10;                    // tensor 0..5
    const float* src;
    switch (t) {
        case 0: src = w0; break;  case 1: src = w1; break;
        case 2: src = w2; break;  case 3: src = w3; break;
        case 4: src = w4; break;  default: src = w5; break;
    }
    const long long e4 = (long long)(b & 1023) * 256 + threadIdx.x;  // float4 index in tensor
    float4 v = *(const float4*)(src + e4 * 4);
    v.x = __uint_as_float(f2tf32(v.x));
    v.y = __uint_as_float(f2tf32(v.y));
    v.z = __uint_as_float(f2tf32(v.z));
    v.w = __uint_as_float(f2tf32(v.w));
    *(float4*)(dst + (long long)t * 1048576 + e4 * 4) = v;
}

// ---------------------------------------------------------------------------
// TF32 tensor-core GEMM body. 2-stage cp.async, TBK=32, 128 thr = 4 warps (2x2),
// warp tile 64x64, mma m16n8k8 tf32.
//   AMODE 0: A [M,K] rm          AMODE 1: A [K,M] rm (A^T)
//   BMODE 0: B [N,K] rm (B^T)    BMODE 1: B [K,N] rm
//   ACVT/BCVT: 1 -> cvt.rna.tf32 on fragment read (operand not pre-rounded)
//   CRND: 1 -> round output to tf32-representable before store
// ---------------------------------------------------------------------------
#define TBM 128
#define TBN 128
#define TBK 32
#define NST 2
#define SMEM_BYTES (NST * (4608 + 4608) * 4)   // worst-case layouts

template<int AMODE, int BMODE, int ACVT, int BCVT, int CRND>
__device__ __forceinline__ void gemm_body(
    float* __restrict__ smem,
    const float* __restrict__ Ab, const float* __restrict__ Bb,
    float* __restrict__ Cb, const float* __restrict__ R,
    int K, int lda, int ldb, int ldc, float alpha,
    int row0, int col0)
{
    constexpr int AS = (AMODE == 0) ? 36 : 136;
    constexpr int BS = (BMODE == 0) ? 36 : 136;
    constexpr int ASZ = (AMODE == 0) ? 128 * 36 : 32 * 136;
    constexpr int BSZ = (BMODE == 0) ? 128 * 36 : 32 * 136;

    float* sA = smem;
    float* sB = smem + NST * ASZ;

    const int tid  = threadIdx.x;
    const int lane = tid & 31;
    const int warp = tid >> 5;          // 0..3
    const int wm = (warp >> 1) * 64;
    const int wn = (warp & 1) * 64;
    const int g  = lane >> 2;
    const int t4 = lane & 3;

    float acc[4][8][4];
    #pragma unroll
    for (int i = 0; i < 4; i++)
        #pragma unroll
        for (int j = 0; j < 8; j++)
            #pragma unroll
            for (int k = 0; k < 4; k++) acc[i][j][k] = 0.f;

    const int nIter = K / TBK;

    auto load_stage = [&](int buf, int k0) {
        float* dA = sA + buf * ASZ;
        float* dB = sB + buf * BSZ;
        if (AMODE == 0) {
            #pragma unroll
            for (int it = 0; it < 8; it++) {
                int f = tid + it * 128;
                int row = f >> 3, c4 = (f & 7) * 4;
                cp_async16(&dA[row * AS + c4],
                           Ab + (long long)(row0 + row) * lda + k0 + c4);
            }
        } else {
            #pragma unroll
            for (int it = 0; it < 8; it++) {
                int f = tid + it * 128;
                int k = f >> 5, m4 = (f & 31) * 4;
                cp_async16(&dA[k * AS + m4],
                           Ab + (long long)(k0 + k) * lda + row0 + m4);
            }
        }
        if (BMODE == 0) {
            #pragma unroll
            for (int it = 0; it < 8; it++) {
                int f = tid + it * 128;
                int n = f >> 3, c4 = (f & 7) * 4;
                cp_async16(&dB[n * BS + c4],
                           Bb + (long long)(col0 + n) * ldb + k0 + c4);
            }
        } else {
            #pragma unroll
            for (int it = 0; it < 8; it++) {
                int f = tid + it * 128;
                int k = f >> 5, n4 = (f & 31) * 4;
                cp_async16(&dB[k * BS + n4],
                           Bb + (long long)(k0 + k) * ldb + col0 + n4);
            }
        }
        cp_commit();
    };

    load_stage(0, 0);
    load_stage(1, TBK);

    for (int it = 0; it < nIter; it++) {
        if (it < nIter - 1) asm volatile("cp.async.wait_group 1;" ::: "memory");
        else                asm volatile("cp.async.wait_group 0;" ::: "memory");
        __syncthreads();

        const int cb = it & 1;
        const float* cA = sA + cb * ASZ;
        const float* cB = sB + cb * BSZ;
        #pragma unroll
        for (int kk = 0; kk < TBK; kk += 8) {
            uint32_t a[4][4], b[8][2];
            #pragma unroll
            for (int mt = 0; mt < 4; mt++) {
                int mb = wm + mt * 16;
                float f0, f1, f2, f3;
                if (AMODE == 0) {
                    f0 = cA[(mb + g) * AS + kk + t4];
                    f1 = cA[(mb + g + 8) * AS + kk + t4];
                    f2 = cA[(mb + g) * AS + kk + t4 + 4];
                    f3 = cA[(mb + g + 8) * AS + kk + t4 + 4];
                } else {
                    f0 = cA[(kk + t4) * AS + mb + g];
                    f1 = cA[(kk + t4) * AS + mb + g + 8];
                    f2 = cA[(kk + t4 + 4) * AS + mb + g];
                    f3 = cA[(kk + t4 + 4) * AS + mb + g + 8];
                }
                if (ACVT) {
                    a[mt][0] = f2tf32(f0); a[mt][1] = f2tf32(f1);
                    a[mt][2] = f2tf32(f2); a[mt][3] = f2tf32(f3);
                } else {
                    a[mt][0] = __float_as_uint(f0); a[mt][1] = __float_as_uint(f1);
                    a[mt][2] = __float_as_uint(f2); a[mt][3] = __float_as_uint(f3);
                }
            }
            #pragma unroll
            for (int nt = 0; nt < 8; nt++) {
                int nb = wn + nt * 8 + g;
                float f0, f1;
                if (BMODE == 0) {
                    f0 = cB[nb * BS + kk + t4];
                    f1 = cB[nb * BS + kk + t4 + 4];
                } else {
                    f0 = cB[(kk + t4) * BS + nb];
                    f1 = cB[(kk + t4 + 4) * BS + nb];
                }
                if (BCVT) { b[nt][0] = f2tf32(f0); b[nt][1] = f2tf32(f1); }
                else      { b[nt][0] = __float_as_uint(f0); b[nt][1] = __float_as_uint(f1); }
            }
            #pragma unroll
            for (int mt = 0; mt < 4; mt++)
                #pragma unroll
                for (int nt = 0; nt < 8; nt++) {
                    asm volatile(
                        "mma.sync.aligned.m16n8k8.row.col.f32.tf32.tf32.f32 "
                        "{%0,%1,%2,%3}, {%4,%5,%6,%7}, {%8,%9}, {%0,%1,%2,%3};"
                        : "+f"(acc[mt][nt][0]), "+f"(acc[mt][nt][1]),
                          "+f"(acc[mt][nt][2]), "+f"(acc[mt][nt][3])
                        : "r"(a[mt][0]), "r"(a[mt][1]), "r"(a[mt][2]), "r"(a[mt][3]),
                          "r"(b[nt][0]), "r"(b[nt][1]));
                }
        }
        __syncthreads();
        if (it + NST < nIter) load_stage(cb, (it + NST) * TBK);
    }

    #pragma unroll
    for (int mt = 0; mt < 4; mt++) {
        int r0g = row0 + wm + mt * 16 + g;
        #pragma unroll
        for (int nt = 0; nt < 8; nt++) {
            int c0g = col0 + wn + nt * 8 + t4 * 2;
            float v0 = acc[mt][nt][0] * alpha;
            float v1 = acc[mt][nt][1] * alpha;
            float v2 = acc[mt][nt][2] * alpha;
            float v3 = acc[mt][nt][3] * alpha;
            if (R) {
                v0 += R[(long long)r0g * ldc + c0g];
                v1 += R[(long long)r0g * ldc + c0g + 1];
                v2 += R[(long long)(r0g + 8) * ldc + c0g];
                v3 += R[(long long)(r0g + 8) * ldc + c0g + 1];
            }
            if (CRND) {
                v0 = __uint_as_float(f2tf32(v0));
                v1 = __uint_as_float(f2tf32(v1));
                v2 = __uint_as_float(f2tf32(v2));
                v3 = __uint_as_float(f2tf32(v3));
            }
            *(float2*)(Cb + (long long)r0g * ldc + c0g)       = make_float2(v0, v1);
            *(float2*)(Cb + (long long)(r0g + 8) * ldc + c0g) = make_float2(v2, v3);
        }
    }
}

__device__ __forceinline__ long long zoff(int z, int div, long long shi, long long slo) {
    return (long long)(z / div) * shi + (long long)(z % div) * slo;
}

template<int AMODE, int BMODE, int ACVT, int BCVT, int CRND>
__global__ void __launch_bounds__(128, 2)
mma_gemm(const float* __restrict__ A, const float* __restrict__ B,
         float* __restrict__ C, const float* __restrict__ R,
         int K, int lda, int ldb, int ldc,
         int adiv, long long ahi, long long alo,
         int bdiv, long long bhi, long long blo,
         int cdiv, long long chi, long long clo,
         float alpha) {
    extern __shared__ float dynsmem[];
    const int z = blockIdx.z;
    gemm_body<AMODE, BMODE, ACVT, BCVT, CRND>(dynsmem,
                            A + zoff(z, adiv, ahi, alo),
                            B + zoff(z, bdiv, bhi, blo),
                            C + zoff(z, cdiv, chi, clo), R,
                            K, lda, ldb, ldc, alpha,
                            blockIdx.y * TBM, blockIdx.x * TBN);
}

// All 5 projections in one launch. z in [0,160): p = z/32, zz = z%32 = (b,h).
// Weights come pre-rounded from g_w[p]. Output rounded (CRND).
__global__ void __launch_bounds__(128, 2)
proj_gemm(const float* x0, const float* x1, const float* x2, const float* x3, const float* x4,
          const float* wr,
          float* c0, float* c1, float* c2, float* c3, float* c4) {
    extern __shared__ float dynsmem[];
    const int z = blockIdx.z;
    const int p = z >> 5, zz = z & 31;
    const float* X; float* C;
    switch (p) {
        case 0: X = x0; C = c0; break;
        case 1: X = x1; C = c1; break;
        case 2: X = x2; C = c2; break;
        case 3: X = x3; C = c3; break;
        default: X = x4; C = c4; break;
    }
    const float* W = wr + (long long)p * 1048576 + (long long)(zz & 7) * DKk * Dd;
    gemm_body<0, 0, 1, 0, 1>(dynsmem,
                    X + (long long)(zz >> 3) * Nn * Dd, W,
                    C + (long long)zz * Nn * DKk, nullptr,
                    Dd, Dd, Dd, DKk, 1.0f, blockIdx.y * TBM, 0);
}

// Merged: time-attn logits (2048 tiles) + feature-attn split-K partials (256 tiles).
// All operands pre-rounded -> no cvt in inner loop.
__global__ void __launch_bounds__(128, 2)
fused_logits(const float* __restrict__ qt, const float* __restrict__ kt,
             const float* __restrict__ qf, const float* __restrict__ kf,
             float* __restrict__ at, float* __restrict__ afp, float alpha) {
    extern __shared__ float dynsmem[];
    const int bx = blockIdx.x;
    if (bx < 2048) {
        const int z = bx >> 6, rem = bx & 63;
        gemm_body<0, 0, 0, 0, 0>(dynsmem,
                        qt + (long long)z * Nn * DKk,
                        kt + (long long)z * Nn * DKk,
                        at + (long long)z * Nn * Nn, nullptr,
                        DKk, DKk, DKk, Nn, alpha,
                        (rem >> 3) * TBM, (rem & 7) * TBN);
    } else {
        const int e = bx - 2048;           // 0..255: z*8 + sub
        const int z = e >> 3, sub = e & 7;
        const long long base = (long long)z * Nn * DKk + (long long)sub * 128 * DKk;
        gemm_body<1, 1, 0, 0, 0>(dynsmem,
                        qf + base, kf + base,
                        afp + (long long)e * DKk * DKk, nullptr,
                        128, DKk, DKk, DKk, alpha, 0, 0);
    }
}

// ---------------------------------------------------------------------------
__device__ __forceinline__ float block_reduce(float v, bool is_max) {
    __shared__ float sh[32];
    int lane = threadIdx.x & 31, w = threadIdx.x >> 5;
    #pragma unroll
    for (int o = 16; o > 0; o >>= 1) {
        float o2 = __shfl_xor_sync(0xffffffff, v, o);
        v = is_max ? fmaxf(v, o2) : v + o2;
    }
    if (lane == 0) sh[w] = v;
    __syncthreads();
    int nw = (blockDim.x + 31) >> 5;
    v = (lane < nw) ? sh[lane] : (is_max ? -3.4e38f : 0.f);
    if (w == 0) {
        #pragma unroll
        for (int o = 16; o > 0; o >>= 1) {
            float o2 = __shfl_xor_sync(0xffffffff, v, o);
            v = is_max ? fmaxf(v, o2) : v + o2;
        }
        if (lane == 0) sh[0] = v;
    }
    __syncthreads();
    v = sh[0];
    __syncthreads();
    return v;
}

__global__ void softmax_time_kernel(float* __restrict__ attn, const int* __restrict__ mask) {
    const int r = blockIdx.x;
    const int b = r / (Hh * Nn);
    const int n = r % Nn;
    float* row = attn + (long long)r * Nn;
    const int* mrow = mask + ((long long)b * Nn + n) * Nn;
    const int t = threadIdx.x;

    float x[4];
    float mx = -3.4e38f;
    #pragma unroll
    for (int i = 0; i < 4; i++) {
        int j = t + i * 256;
        float v = row[j];
        if (mrow[j] == 0) v = -1e9f;
        x[i] = v;
        mx = fmaxf(mx, v);
    }
    mx = block_reduce(mx, true);
    float s = 0.f;
    #pragma unroll
    for (int i = 0; i < 4; i++) { x[i] = __expf(x[i] - mx); s += x[i]; }
    s = block_reduce(s, false);
    float inv = 1.f / s;
    #pragma unroll
    for (int i = 0; i < 4; i++) row[t + i * 256] = x[i] * inv;
}

// reduce 8 split-K partials + softmax over last axis. block = (z,row), 128 thr.
__global__ void softmax_feat_kernel(const float* __restrict__ afp, float* __restrict__ S) {
    const int z = blockIdx.x >> 7;
    const int row = blockIdx.x & 127;
    const int t = threadIdx.x;
    float v = 0.f;
    #pragma unroll
    for (int s8 = 0; s8 < 8; s8++)
        v += afp[(((long long)z * 8 + s8) * DKk + row) * DKk + t];
    float mx = block_reduce(v, true);
    float e = __expf(v - mx);
    float s = block_reduce(e, false);
    S[((long long)z * DKk + row) * DKk + t] = e / s;
}

__global__ void layernorm_kernel(const float* __restrict__ X, float* __restrict__ O,
                                 const float* __restrict__ gamma, const float* __restrict__ beta) {
    const int r = blockIdx.x;
    const float* row = X + (long long)r * Dd;
    float* orow = O + (long long)r * Dd;
    const int t = threadIdx.x;
    float x[4];
    float s = 0.f, s2 = 0.f;
    #pragma unroll
    for (int i = 0; i < 4; i++) {
        x[i] = row[t + i * 256];
        s += x[i];
        s2 += x[i] * x[i];
    }
    s = block_reduce(s, false);
    s2 = block_reduce(s2, false);
    float mean = s * (1.f / Dd);
    float var = s2 * (1.f / Dd) - mean * mean;
    float inv = rsqrtf(var + EPSf);
    #pragma unroll
    for (int i = 0; i < 4; i++) {
        int j = t + i * 256;
        orow[j] = (x[i] - mean) * inv * gamma[j] + beta[j];
    }
}

// ---------------------------------------------------------------------------
extern "C" void kernel_launch(void* const* d_in, const int* in_sizes, int n_in,
                              void* d_out, int out_size) {
    const float* q_time    = (const float*)d_in[0];
    const float* k_time    = (const float*)d_in[1];
    const float* q_feature = (const float*)d_in[2];
    const float* k_feature = (const float*)d_in[3];
    const float* v         = (const float*)d_in[4];
    const int*   attn_mask = (const int*)  d_in[5];
    const float* w_qs_time = (const float*)d_in[6];
    const float* w_ks_time = (const float*)d_in[7];
    const float* w_qs_feat = (const float*)d_in[8];
    const float* w_ks_feat = (const float*)d_in[9];
    const float* w_vs      = (const float*)d_in[10];
    const float* w_fc      = (const float*)d_in[11];
    const float* ln_gamma  = (const float*)d_in[12];
    const float* ln_beta   = (const float*)d_in[13];
    float* out = (float*)d_out;

    float *qt, *kt, *qf, *kf, *vv, *o1, *prefc, *preln, *afp, *wr;
    cudaGetSymbolAddress((void**)&qt,    g_qt);
    cudaGetSymbolAddress((void**)&kt,    g_kt);
    cudaGetSymbolAddress((void**)&qf,    g_qf);
    cudaGetSymbolAddress((void**)&kf,    g_kf);
    cudaGetSymbolAddress((void**)&vv,    g_vv);
    cudaGetSymbolAddress((void**)&o1,    g_o1);
    cudaGetSymbolAddress((void**)&prefc, g_prefc);
    cudaGetSymbolAddress((void**)&preln, g_preln);
    cudaGetSymbolAddress((void**)&afp,   g_afp);
    cudaGetSymbolAddress((void**)&wr,    g_w);

    cudaFuncSetAttribute(proj_gemm, cudaFuncAttributeMaxDynamicSharedMemorySize, SMEM_BYTES);
    cudaFuncSetAttribute(fused_logits, cudaFuncAttributeMaxDynamicSharedMemorySize, SMEM_BYTES);
    cudaFuncSetAttribute((const void*)mma_gemm<0, 1, 1, 0, 1>, cudaFuncAttributeMaxDynamicSharedMemorySize, SMEM_BYTES);
    cudaFuncSetAttribute((const void*)mma_gemm<0, 1, 0, 1, 1>, cudaFuncAttributeMaxDynamicSharedMemorySize, SMEM_BYTES);
    cudaFuncSetAttribute((const void*)mma_gemm<0, 0, 0, 0, 0>, cudaFuncAttributeMaxDynamicSharedMemorySize, SMEM_BYTES);

    const float inv_temp = 1.0f / sqrtf((float)DKk);
    const int Z = Bz * Hh;  // 32
    dim3 blk(128);

    // 0) pre-round weights to tf32-representable fp32
    round_w_kernel<<<6 * 1024, 256>>>(w_qs_time, w_ks_time, w_qs_feat, w_ks_feat,
                                      w_vs, w_fc, wr);

    // 1) all projections (A needs cvt, W pre-rounded, outputs rounded)
    {
        dim3 grid(1, Nn / TBM, 5 * Z);
        proj_gemm<<<grid, blk, SMEM_BYTES>>>(q_time, k_time, q_feature, k_feature, v,
                                             wr, qt, kt, qf, kf, vv);
    }

    float* at = out + AT_OFF;
    float* af = out + AF_OFF;

    // 2) time logits + feature split-K partials (all operands pre-rounded)
    fused_logits<<<2048 + 256, blk, SMEM_BYTES>>>(qt, kt, qf, kf, at, afp, inv_temp);

    // 3) softmaxes
    softmax_time_kernel<<<Bz * Hh * Nn, 256>>>(at, attn_mask);
    softmax_feat_kernel<<<Z * DKk, 128>>>(afp, af);

    // 4) o1[z] = softmax(at)[z] @ vv[z] (A=softmax out needs cvt; B rounded; C rounded)
    {
        dim3 grid(1, Nn / TBM, Z);
        mma_gemm<0, 1, 1, 0, 1><<<grid, blk, SMEM_BYTES>>>(at, vv, o1, nullptr,
                                      Nn, Nn, DKk, DKk,
                                      1, (long long)Nn * Nn, 0,
                                      1, (long long)Nn * DKk, 0,
                                      1, (long long)Nn * DKk, 0, 1.0f);
    }

    // 5) prefc = o1 @ af (A rounded; B=softmax out needs cvt; C rounded)
    {
        dim3 grid(1, Nn / TBM, Z);
        mma_gemm<0, 1, 0, 1, 1><<<grid, blk, SMEM_BYTES>>>(o1, af, prefc, nullptr,
                                      DKk, DKk, DKk, Dd,
                                      1, (long long)Nn * DKk, 0,
                                      1, (long long)DKk * DKk, 0,
                                      Hh, (long long)Nn * Dd, DKk, 1.0f);
    }

    // 6) preln = prefc @ w_fc_rounded^T + v (both rounded; residual = original v)
    {
        dim3 grid(Dd / TBN, (Bz * Nn) / TBM, 1);
        mma_gemm<0, 0, 0, 0, 0><<<grid, blk, SMEM_BYTES>>>(prefc, wr + 5u * 1048576u, preln, v,
                                      Dd, Dd, Dd, Dd,
                                      1, 0, 0, 1, 0, 0, 1, 0, 0, 1.0f);
    }

    // 7) LayerNorm
    layernorm_kernel<<<Bz * Nn, 256>>>(preln, out, ln_gamma, ln_beta);
}

// round 6
// speedup vs baseline: 13.5449x; 1.4381x over previous
#include <cuda_runtime.h>
#include <cuda_fp16.h>
#include <math.h>
#include <stdint.h>

// Problem constants
#define Bz   4
#define Nn   1024
#define Dd   1024
#define Hh   8
#define DKk  128
#define EPSf 1e-6f

static const long long AT_OFF  = (long long)Bz * Nn * Dd;                 // 4194304
static const long long AF_OFF  = AT_OFF + (long long)Bz * Hh * Nn * Nn;  // 37748736

#define PROJ_ELEMS ((long long)Bz * Hh * Nn * DKk)   // 4194304
__device__ __half g_qt[PROJ_ELEMS];
__device__ __half g_kt[PROJ_ELEMS];
__device__ __half g_qf[PROJ_ELEMS];
__device__ __half g_kf[PROJ_ELEMS];
__device__ __half g_vvT[PROJ_ELEMS];                  // [z][d][n] transposed
__device__ __half g_o1[PROJ_ELEMS];
__device__ __half g_prefc[(long long)Bz * Nn * Dd];
__device__ float  g_preln[(long long)Bz * Nn * Dd];
__device__ float  g_afp[(long long)32 * 8 * DKk * DKk];     // split-K partials
__device__ __half g_at16[(long long)Bz * Hh * Nn * Nn];     // fp16 attn copy
__device__ __half g_af16[(long long)32 * DKk * DKk];        // fp16 feat-attn copy
__device__ __half g_wh[6u * 1048576u];                      // fp16 weights

__device__ __forceinline__ void cp_async16(void* dst, const void* src) {
    uint32_t s = (uint32_t)__cvta_generic_to_shared(dst);
    asm volatile("cp.async.cg.shared.global [%0], [%1], 16;" :: "r"(s), "l"(src));
}
__device__ __forceinline__ void cp_commit() {
    asm volatile("cp.async.commit_group;" ::: "memory");
}
__device__ __forceinline__ uint32_t pack_h2(const __half* lo, const __half* hi) {
    uint32_t u0 = *(const unsigned short*)lo;
    uint32_t u1 = *(const unsigned short*)hi;
    return u0 | (u1 << 16);
}
__device__ __forceinline__ uint32_t f2_to_h2(float x, float y) {
    __half2 h = __floats2half2_rn(x, y);
    return *(uint32_t*)&h;
}

// Convert 6 weight matrices (1M floats each) to fp16.
__global__ void cvt_w_kernel(const float* w0, const float* w1, const float* w2,
                             const float* w3, const float* w4, const float* w5,
                             __half* dst) {
    const int b = blockIdx.x;                 // 0..6143
    const int t = b >> 10;
    const float* src;
    switch (t) {
        case 0: src = w0; break;  case 1: src = w1; break;
        case 2: src = w2; break;  case 3: src = w3; break;
        case 4: src = w4; break;  default: src = w5; break;
    }
    const long long e4 = (long long)(b & 1023) * 256 + threadIdx.x;
    float4 v = *(const float4*)(src + e4 * 4);
    uint32_t lo = f2_to_h2(v.x, v.y), hi = f2_to_h2(v.z, v.w);
    *(uint2*)(dst + (long long)t * 1048576 + e4 * 4) = make_uint2(lo, hi);
}

// ---------------------------------------------------------------------------
// FP16 tensor-core GEMM body. cp.async pipeline (NSTG stages), TBK=32,
// 128 thr = 4 warps (2x2), warp tile 64x64, mma m16n8k16 f16 -> f32 accum.
//   AMODE 0: A [M,K] rm          AMODE 1: A [K,M] rm (A^T)
//   BMODE 0: B [N,K] rm (B^T)    BMODE 1: B [K,N] rm
//   ACVT 1: A gmem/smem is fp32, convert at fragment read (AMODE0 only)
//   CH   1: write C as fp16 (else fp32, with optional fp32 residual R)
//   CT   1: write transposed fp16 C via smem staging (Ct [N][M-range])
// ---------------------------------------------------------------------------
#define TBM 128
#define TBN 128
#define TBK 32
#define SMEM_ALL 61440

template<int AMODE, int BMODE, int ACVT, int CH, int CT, int NSTG>
__device__ __forceinline__ void gemm_f16(
    char* __restrict__ smem,
    const void* __restrict__ Ab, const __half* __restrict__ Bb,
    void* __restrict__ Cb, const float* __restrict__ R,
    __half* __restrict__ Ct, int ldt,
    int K, int lda, int ldb, int ldc, float alpha,
    int row0, int col0)
{
    constexpr int AS  = (AMODE == 0) ? 40 : 136;   // element stride in smem
    constexpr int BS  = (BMODE == 0) ? 40 : 136;
    constexpr int ASZB = ACVT ? 128 * 40 * 4 : ((AMODE == 0) ? 128 * 40 * 2 : 32 * 136 * 2);
    constexpr int BSZB = (BMODE == 0) ? 128 * 40 * 2 : 32 * 136 * 2;

    char* sAb = smem;
    char* sBb = smem + NSTG * ASZB;

    const int tid  = threadIdx.x;
    const int lane = tid & 31;
    const int warp = tid >> 5;
    const int wm = (warp >> 1) * 64;
    const int wn = (warp & 1) * 64;
    const int g  = lane >> 2;
    const int t4 = lane & 3;

    float acc[4][8][4];
    #pragma unroll
    for (int i = 0; i < 4; i++)
        #pragma unroll
        for (int j = 0; j < 8; j++)
            #pragma unroll
            for (int k = 0; k < 4; k++) acc[i][j][k] = 0.f;

    const int nIter = K / TBK;

    auto load_stage = [&](int buf, int k0) {
        if (ACVT) {
            float* dA = (float*)(sAb + buf * ASZB);
            const float* Ag = (const float*)Ab;
            #pragma unroll
            for (int it = 0; it < 8; it++) {
                int f = tid + it * 128;
                int row = f >> 3, seg = (f & 7) * 4;
                cp_async16(&dA[row * 40 + seg], Ag + (long long)(row0 + row) * lda + k0 + seg);
            }
        } else if (AMODE == 0) {
            __half* dA = (__half*)(sAb + buf * ASZB);
            const __half* Ag = (const __half*)Ab;
            #pragma unroll
            for (int it = 0; it < 4; it++) {
                int f = tid + it * 128;
                int row = f >> 2, seg = (f & 3) * 8;
                cp_async16(&dA[row * 40 + seg], Ag + (long long)(row0 + row) * lda + k0 + seg);
            }
        } else {
            __half* dA = (__half*)(sAb + buf * ASZB);
            const __half* Ag = (const __half*)Ab;
            #pragma unroll
            for (int it = 0; it < 4; it++) {
                int f = tid + it * 128;
                int k = f >> 4, seg = (f & 15) * 8;
                cp_async16(&dA[k * 136 + seg], Ag + (long long)(k0 + k) * lda + row0 + seg);
            }
        }
        if (BMODE == 0) {
            __half* dB = (__half*)(sBb + buf * BSZB);
            #pragma unroll
            for (int it = 0; it < 4; it++) {
                int f = tid + it * 128;
                int row = f >> 2, seg = (f & 3) * 8;
                cp_async16(&dB[row * 40 + seg], Bb + (long long)(col0 + row) * ldb + k0 + seg);
            }
        } else {
            __half* dB = (__half*)(sBb + buf * BSZB);
            #pragma unroll
            for (int it = 0; it < 4; it++) {
                int f = tid + it * 128;
                int k = f >> 4, seg = (f & 15) * 8;
                cp_async16(&dB[k * 136 + seg], Bb + (long long)(k0 + k) * ldb + col0 + seg);
            }
        }
        cp_commit();
    };

    #pragma unroll
    for (int s = 0; s < NSTG; s++) load_stage(s, s * TBK);

    for (int it = 0; it < nIter; it++) {
        const int rem = nIter - 1 - it;
        if (NSTG == 3) {
            if (rem >= 2)      asm volatile("cp.async.wait_group 2;" ::: "memory");
            else if (rem == 1) asm volatile("cp.async.wait_group 1;" ::: "memory");
            else               asm volatile("cp.async.wait_group 0;" ::: "memory");
        } else {
            if (rem >= 1)      asm volatile("cp.async.wait_group 1;" ::: "memory");
            else               asm volatile("cp.async.wait_group 0;" ::: "memory");
        }
        __syncthreads();

        const int cb = it % NSTG;
        const char* cAb = sAb + cb * ASZB;
        const char* cBb = sBb + cb * BSZB;

        #pragma unroll
        for (int kk = 0; kk < TBK; kk += 16) {
            uint32_t a[4][4], b[8][2];
            #pragma unroll
            for (int mt = 0; mt < 4; mt++) {
                int mb = wm + mt * 16;
                if (ACVT) {
                    const float* cA = (const float*)cAb;
                    float2 p0 = *(const float2*)&cA[(mb + g) * 40 + kk + 2 * t4];
                    float2 p1 = *(const float2*)&cA[(mb + g + 8) * 40 + kk + 2 * t4];
                    float2 p2 = *(const float2*)&cA[(mb + g) * 40 + kk + 2 * t4 + 8];
                    float2 p3 = *(const float2*)&cA[(mb + g + 8) * 40 + kk + 2 * t4 + 8];
                    a[mt][0] = f2_to_h2(p0.x, p0.y);
                    a[mt][1] = f2_to_h2(p1.x, p1.y);
                    a[mt][2] = f2_to_h2(p2.x, p2.y);
                    a[mt][3] = f2_to_h2(p3.x, p3.y);
                } else if (AMODE == 0) {
                    const __half* cA = (const __half*)cAb;
                    a[mt][0] = *(const uint32_t*)&cA[(mb + g) * 40 + kk + 2 * t4];
                    a[mt][1] = *(const uint32_t*)&cA[(mb + g + 8) * 40 + kk + 2 * t4];
                    a[mt][2] = *(const uint32_t*)&cA[(mb + g) * 40 + kk + 2 * t4 + 8];
                    a[mt][3] = *(const uint32_t*)&cA[(mb + g + 8) * 40 + kk + 2 * t4 + 8];
                } else {
                    const __half* cA = (const __half*)cAb;
                    int kr = kk + 2 * t4;
                    a[mt][0] = pack_h2(&cA[kr * 136 + mb + g],       &cA[(kr + 1) * 136 + mb + g]);
                    a[mt][1] = pack_h2(&cA[kr * 136 + mb + g + 8],   &cA[(kr + 1) * 136 + mb + g + 8]);
                    a[mt][2] = pack_h2(&cA[(kr + 8) * 136 + mb + g], &cA[(kr + 9) * 136 + mb + g]);
                    a[mt][3] = pack_h2(&cA[(kr + 8) * 136 + mb + g + 8], &cA[(kr + 9) * 136 + mb + g + 8]);
                }
            }
            #pragma unroll
            for (int nt = 0; nt < 8; nt++) {
                int nb = wn + nt * 8 + g;
                if (BMODE == 0) {
                    const __half* cB = (const __half*)cBb;
                    b[nt][0] = *(const uint32_t*)&cB[nb * 40 + kk + 2 * t4];
                    b[nt][1] = *(const uint32_t*)&cB[nb * 40 + kk + 2 * t4 + 8];
                } else {
                    const __half* cB = (const __half*)cBb;
                    int kr = kk + 2 * t4;
                    b[nt][0] = pack_h2(&cB[kr * 136 + nb],       &cB[(kr + 1) * 136 + nb]);
                    b[nt][1] = pack_h2(&cB[(kr + 8) * 136 + nb], &cB[(kr + 9) * 136 + nb]);
                }
            }
            #pragma unroll
            for (int mt = 0; mt < 4; mt++)
                #pragma unroll
                for (int nt = 0; nt < 8; nt++) {
                    asm volatile(
                        "mma.sync.aligned.m16n8k16.row.col.f32.f16.f16.f32 "
                        "{%0,%1,%2,%3}, {%4,%5,%6,%7}, {%8,%9}, {%0,%1,%2,%3};"
                        : "+f"(acc[mt][nt][0]), "+f"(acc[mt][nt][1]),
                          "+f"(acc[mt][nt][2]), "+f"(acc[mt][nt][3])
                        : "r"(a[mt][0]), "r"(a[mt][1]), "r"(a[mt][2]), "r"(a[mt][3]),
                          "r"(b[nt][0]), "r"(b[nt][1]));
                }
        }
        __syncthreads();
        if (it + NSTG < nIter) load_stage(cb, (it + NSTG) * TBK);
    }

    if (CT) {
        // transposed fp16 epilogue via smem staging: st[c][m_local], stride 136
        __half* st = (__half*)smem;
        #pragma unroll
        for (int mt = 0; mt < 4; mt++) {
            int rl = wm + mt * 16 + g;
            #pragma unroll
            for (int nt = 0; nt < 8; nt++) {
                int c = wn + nt * 8 + t4 * 2;
                st[c * 136 + rl]            = __float2half_rn(acc[mt][nt][0] * alpha);
                st[(c + 1) * 136 + rl]      = __float2half_rn(acc[mt][nt][1] * alpha);
                st[c * 136 + rl + 8]        = __float2half_rn(acc[mt][nt][2] * alpha);
                st[(c + 1) * 136 + rl + 8]  = __float2half_rn(acc[mt][nt][3] * alpha);
            }
        }
        __syncthreads();
        #pragma unroll
        for (int it2 = 0; it2 < 16; it2++) {
            int i = tid + it2 * 128;
            int d = i >> 4, seg = (i & 15) * 8;
            *(uint4*)(Ct + (long long)d * ldt + row0 + seg) = *(const uint4*)&st[d * 136 + seg];
        }
        return;
    }

    #pragma unroll
    for (int mt = 0; mt < 4; mt++) {
        int r0g = row0 + wm + mt * 16 + g;
        #pragma unroll
        for (int nt = 0; nt < 8; nt++) {
            int c0g = col0 + wn + nt * 8 + t4 * 2;
            float v0 = acc[mt][nt][0] * alpha;
            float v1 = acc[mt][nt][1] * alpha;
            float v2 = acc[mt][nt][2] * alpha;
            float v3 = acc[mt][nt][3] * alpha;
            if (CH) {
                __half* Ch = (__half*)Cb;
                *(uint32_t*)(Ch + (long long)r0g * ldc + c0g)       = f2_to_h2(v0, v1);
                *(uint32_t*)(Ch + (long long)(r0g + 8) * ldc + c0g) = f2_to_h2(v2, v3);
            } else {
                float* Cf = (float*)Cb;
                if (R) {
                    v0 += R[(long long)r0g * ldc + c0g];
                    v1 += R[(long long)r0g * ldc + c0g + 1];
                    v2 += R[(long long)(r0g + 8) * ldc + c0g];
                    v3 += R[(long long)(r0g + 8) * ldc + c0g + 1];
                }
                *(float2*)(Cf + (long long)r0g * ldc + c0g)       = make_float2(v0, v1);
                *(float2*)(Cf + (long long)(r0g + 8) * ldc + c0g) = make_float2(v2, v3);
            }
        }
    }
}

// ---------------------------------------------------------------------------
// Kernels
// ---------------------------------------------------------------------------

// All 5 projections. z in [0,160): p = z/32, zz = z%32 = (b,h). A = fp32 input
// (ACVT), B = fp16 weights. p<4 -> fp16 [n][128]; p==4 -> transposed vvT.
__global__ void __launch_bounds__(128, 3)
proj_gemm(const float* x0, const float* x1, const float* x2, const float* x3, const float* x4,
          const __half* wh,
          __half* qt, __half* kt, __half* qf, __half* kf, __half* vvT) {
    extern __shared__ char dynsmem[];
    const int z = blockIdx.z;
    const int p = z >> 5, zz = z & 31;
    const float* X;
    switch (p) {
        case 0: X = x0; break;  case 1: X = x1; break;
        case 2: X = x2; break;  case 3: X = x3; break;
        default: X = x4; break;
    }
    const float* Ab = X + (long long)(zz >> 3) * Nn * Dd;
    const __half* Bb = wh + (long long)p * 1048576 + (long long)(zz & 7) * DKk * Dd;
    const int row0 = blockIdx.y * TBM;
    if (p == 4) {
        gemm_f16<0, 0, 1, 1, 1, 2>(dynsmem, Ab, Bb, nullptr, nullptr,
                                   vvT + (long long)zz * DKk * Nn, Nn,
                                   Dd, Dd, Dd, DKk, 1.0f, row0, 0);
    } else {
        __half* C;
        switch (p) {
            case 0: C = qt; break;  case 1: C = kt; break;
            case 2: C = qf; break;  default: C = kf; break;
        }
        gemm_f16<0, 0, 1, 1, 0, 2>(dynsmem, Ab, Bb,
                                   C + (long long)zz * Nn * DKk, nullptr, nullptr, 0,
                                   Dd, Dd, Dd, DKk, 1.0f, row0, 0);
    }
}

// time logits (2048 tiles, fp32 out) + feature split-K partials (256 tiles).
__global__ void __launch_bounds__(128, 3)
fused_logits(const __half* __restrict__ qt, const __half* __restrict__ kt,
             const __half* __restrict__ qf, const __half* __restrict__ kf,
             float* __restrict__ at, float* __restrict__ afp, float alpha) {
    extern __shared__ char dynsmem[];
    const int bx = blockIdx.x;
    if (bx < 2048) {
        const int z = bx >> 6, rem = bx & 63;
        gemm_f16<0, 0, 0, 0, 0, 3>(dynsmem,
                        qt + (long long)z * Nn * DKk,
                        kt + (long long)z * Nn * DKk,
                        at + (long long)z * Nn * Nn, nullptr, nullptr, 0,
                        DKk, DKk, DKk, Nn, alpha,
                        (rem >> 3) * TBM, (rem & 7) * TBN);
    } else {
        const int e = bx - 2048;
        const int z = e >> 3, sub = e & 7;
        const long long base = (long long)z * Nn * DKk + (long long)sub * 128 * DKk;
        gemm_f16<1, 1, 0, 0, 0, 3>(dynsmem,
                        qf + base, kf + base,
                        afp + (long long)e * DKk * DKk, nullptr, nullptr, 0,
                        128, DKk, DKk, DKk, alpha, 0, 0);
    }
}

// o1[z] = at16[z] @ vvT[z]^T : A [n][m] fp16, B [d][m] fp16 -> o1 fp16 [n][d]
__global__ void __launch_bounds__(128, 3)
attnv_gemm(const __half* __restrict__ at16, const __half* __restrict__ vvT,
           __half* __restrict__ o1) {
    extern __shared__ char dynsmem[];
    const int z = blockIdx.z;
    gemm_f16<0, 0, 0, 1, 0, 3>(dynsmem,
                    at16 + (long long)z * Nn * Nn,
                    vvT + (long long)z * DKk * Nn,
                    o1 + (long long)z * Nn * DKk, nullptr, nullptr, 0,
                    Nn, Nn, Nn, DKk, 1.0f, blockIdx.y * TBM, 0);
}

// prefc[b,n,h*128+e] = o1[z] @ af16[z] : B [d][e] fp16 K-major (BMODE1)
__global__ void __launch_bounds__(128, 3)
prefc_gemm(const __half* __restrict__ o1, const __half* __restrict__ af16,
           __half* __restrict__ prefc) {
    extern __shared__ char dynsmem[];
    const int z = blockIdx.z;
    gemm_f16<0, 1, 0, 1, 0, 3>(dynsmem,
                    o1 + (long long)z * Nn * DKk,
                    af16 + (long long)z * DKk * DKk,
                    prefc + (long long)(z >> 3) * Nn * Dd + (z & 7) * DKk,
                    nullptr, nullptr, 0,
                    DKk, DKk, DKk, Dd, 1.0f, blockIdx.y * TBM, 0);
}

// preln = prefc @ w_fc^T + v
__global__ void __launch_bounds__(128, 3)
fc_gemm(const __half* __restrict__ prefc, const __half* __restrict__ wfc,
        float* __restrict__ preln, const float* __restrict__ v) {
    extern __shared__ char dynsmem[];
    gemm_f16<0, 0, 0, 0, 0, 3>(dynsmem, prefc, wfc, preln, v, nullptr, 0,
                    Dd, Dd, Dd, Dd, 1.0f,
                    blockIdx.y * TBM, blockIdx.x * TBN);
}

// ---------------------------------------------------------------------------
__device__ __forceinline__ float block_reduce(float v, bool is_max) {
    __shared__ float sh[32];
    int lane = threadIdx.x & 31, w = threadIdx.x >> 5;
    #pragma unroll
    for (int o = 16; o > 0; o >>= 1) {
        float o2 = __shfl_xor_sync(0xffffffff, v, o);
        v = is_max ? fmaxf(v, o2) : v + o2;
    }
    if (lane == 0) sh[w] = v;
    __syncthreads();
    int nw = (blockDim.x + 31) >> 5;
    v = (lane < nw) ? sh[lane] : (is_max ? -3.4e38f : 0.f);
    if (w == 0) {
        #pragma unroll
        for (int o = 16; o > 0; o >>= 1) {
            float o2 = __shfl_xor_sync(0xffffffff, v, o);
            v = is_max ? fmaxf(v, o2) : v + o2;
        }
        if (lane == 0) sh[0] = v;
    }
    __syncthreads();
    v = sh[0];
    __syncthreads();
    return v;
}

// masked softmax; writes fp32 (d_out) + fp16 copy. Row = (b,h,n), 256 thr x4.
__global__ void softmax_time_kernel(float* __restrict__ attn, const int* __restrict__ mask,
                                    __half* __restrict__ attn16) {
    const int r = blockIdx.x;
    const int b = r / (Hh * Nn);
    const int n = r % Nn;
    float* row = attn + (long long)r * Nn;
    __half* row16 = attn16 + (long long)r * Nn;
    const int* mrow = mask + ((long long)b * Nn + n) * Nn;
    const int j0 = threadIdx.x * 4;

    float4 xv = *(const float4*)(row + j0);
    int4  mv = *(const int4*)(mrow + j0);
    float x[4] = {mv.x == 0 ? -1e9f : xv.x, mv.y == 0 ? -1e9f : xv.y,
                  mv.z == 0 ? -1e9f : xv.z, mv.w == 0 ? -1e9f : xv.w};
    float mx = fmaxf(fmaxf(x[0], x[1]), fmaxf(x[2], x[3]));
    mx = block_reduce(mx, true);
    float s = 0.f;
    #pragma unroll
    for (int i = 0; i < 4; i++) { x[i] = __expf(x[i] - mx); s += x[i]; }
    s = block_reduce(s, false);
    float inv = 1.f / s;
    #pragma unroll
    for (int i = 0; i < 4; i++) x[i] *= inv;
    *(float4*)(row + j0) = make_float4(x[0], x[1], x[2], x[3]);
    *(uint2*)(row16 + j0) = make_uint2(f2_to_h2(x[0], x[1]), f2_to_h2(x[2], x[3]));
}

// reduce 8 split-K partials + softmax; writes fp32 (d_out) + fp16 copy.
__global__ void softmax_feat_kernel(const float* __restrict__ afp, float* __restrict__ S,
                                    __half* __restrict__ S16) {
    const int z = blockIdx.x >> 7;
    const int row = blockIdx.x & 127;
    const int t = threadIdx.x;
    float v = 0.f;
    #pragma unroll
    for (int s8 = 0; s8 < 8; s8++)
        v += afp[(((long long)z * 8 + s8) * DKk + row) * DKk + t];
    float mx = block_reduce(v, true);
    float e = __expf(v - mx);
    float s = block_reduce(e, false);
    float o = e / s;
    S[((long long)z * DKk + row) * DKk + t] = o;
    S16[((long long)z * DKk + row) * DKk + t] = __float2half_rn(o);
}

__global__ void layernorm_kernel(const float* __restrict__ X, float* __restrict__ O,
                                 const float* __restrict__ gamma, const float* __restrict__ beta) {
    const int r = blockIdx.x;
    const float* row = X + (long long)r * Dd;
    float* orow = O + (long long)r * Dd;
    const int j0 = threadIdx.x * 4;
    float4 xv = *(const float4*)(row + j0);
    float x[4] = {xv.x, xv.y, xv.z, xv.w};
    float s = x[0] + x[1] + x[2] + x[3];
    float s2 = x[0]*x[0] + x[1]*x[1] + x[2]*x[2] + x[3]*x[3];
    s = block_reduce(s, false);
    s2 = block_reduce(s2, false);
    float mean = s * (1.f / Dd);
    float var = s2 * (1.f / Dd) - mean * mean;
    float inv = rsqrtf(var + EPSf);
    float4 gv = *(const float4*)(gamma + j0);
    float4 bv = *(const float4*)(beta + j0);
    float4 ov = make_float4((x[0] - mean) * inv * gv.x + bv.x,
                            (x[1] - mean) * inv * gv.y + bv.y,
                            (x[2] - mean) * inv * gv.z + bv.z,
                            (x[3] - mean) * inv * gv.w + bv.w);
    *(float4*)(orow + j0) = ov;
}

// ---------------------------------------------------------------------------
extern "C" void kernel_launch(void* const* d_in, const int* in_sizes, int n_in,
                              void* d_out, int out_size) {
    const float* q_time    = (const float*)d_in[0];
    const float* k_time    = (const float*)d_in[1];
    const float* q_feature = (const float*)d_in[2];
    const float* k_feature = (const float*)d_in[3];
    const float* v         = (const float*)d_in[4];
    const int*   attn_mask = (const int*)  d_in[5];
    const float* w_qs_time = (const float*)d_in[6];
    const float* w_ks_time = (const float*)d_in[7];
    const float* w_qs_feat = (const float*)d_in[8];
    const float* w_ks_feat = (const float*)d_in[9];
    const float* w_vs      = (const float*)d_in[10];
    const float* w_fc      = (const float*)d_in[11];
    const float* ln_gamma  = (const float*)d_in[12];
    const float* ln_beta   = (const float*)d_in[13];
    float* out = (float*)d_out;

    __half *qt, *kt, *qf, *kf, *vvT, *o1, *prefc, *at16, *af16, *wh;
    float *preln, *afp;
    cudaGetSymbolAddress((void**)&qt,    g_qt);
    cudaGetSymbolAddress((void**)&kt,    g_kt);
    cudaGetSymbolAddress((void**)&qf,    g_qf);
    cudaGetSymbolAddress((void**)&kf,    g_kf);
    cudaGetSymbolAddress((void**)&vvT,   g_vvT);
    cudaGetSymbolAddress((void**)&o1,    g_o1);
    cudaGetSymbolAddress((void**)&prefc, g_prefc);
    cudaGetSymbolAddress((void**)&preln, g_preln);
    cudaGetSymbolAddress((void**)&afp,   g_afp);
    cudaGetSymbolAddress((void**)&at16,  g_at16);
    cudaGetSymbolAddress((void**)&af16,  g_af16);
    cudaGetSymbolAddress((void**)&wh,    g_wh);

    cudaFuncSetAttribute(proj_gemm,   cudaFuncAttributeMaxDynamicSharedMemorySize, SMEM_ALL);
    cudaFuncSetAttribute(fused_logits,cudaFuncAttributeMaxDynamicSharedMemorySize, SMEM_ALL);
    cudaFuncSetAttribute(attnv_gemm,  cudaFuncAttributeMaxDynamicSharedMemorySize, SMEM_ALL);
    cudaFuncSetAttribute(prefc_gemm,  cudaFuncAttributeMaxDynamicSharedMemorySize, SMEM_ALL);
    cudaFuncSetAttribute(fc_gemm,     cudaFuncAttributeMaxDynamicSharedMemorySize, SMEM_ALL);

    const float inv_temp = 1.0f / sqrtf((float)DKk);
    const int Z = Bz * Hh;  // 32
    dim3 blk(128);

    // 0) weights -> fp16
    cvt_w_kernel<<<6 * 1024, 256>>>(w_qs_time, w_ks_time, w_qs_feat, w_ks_feat,
                                    w_vs, w_fc, wh);

    // 1) all projections (fp16 outputs; vv written transposed)
    {
        dim3 grid(1, Nn / TBM, 5 * Z);
        proj_gemm<<<grid, blk, SMEM_ALL>>>(q_time, k_time, q_feature, k_feature, v,
                                           wh, qt, kt, qf, kf, vvT);
    }

    float* at = out + AT_OFF;
    float* af = out + AF_OFF;

    // 2) time logits + feature split-K partials
    fused_logits<<<2048 + 256, blk, SMEM_ALL>>>(qt, kt, qf, kf, at, afp, inv_temp);

    // 3) softmaxes (fp32 d_out + fp16 copies)
    softmax_time_kernel<<<Bz * Hh * Nn, 256>>>(at, attn_mask, at16);
    softmax_feat_kernel<<<Z * DKk, 128>>>(afp, af, af16);

    // 4) o1 = attn @ v
    {
        dim3 grid(1, Nn / TBM, Z);
        attnv_gemm<<<grid, blk, SMEM_ALL>>>(at16, vvT, o1);
    }

    // 5) prefc = o1 @ af
    {
        dim3 grid(1, Nn / TBM, Z);
        prefc_gemm<<<grid, blk, SMEM_ALL>>>(o1, af16, prefc);
    }

    // 6) preln = prefc @ w_fc^T + v
    {
        dim3 grid(Dd / TBN, (Bz * Nn) / TBM, 1);
        fc_gemm<<<grid, blk, SMEM_ALL>>>(prefc, wh + 5u * 1048576u, preln, v);
    }

    // 7) LayerNorm
    layernorm_kernel<<<Bz * Nn, 256>>>(preln, out, ln_gamma, ln_beta);
}